// round 2
// baseline (speedup 1.0000x reference)
#include <cuda_runtime.h>
#include <math.h>

#define NA 4096
#define NB 4096
#define D  256
#define H  4
#define DK 64
#define TA 32
#define TB 32

// Scratch for projected Q/K/V (device globals: no allocation in kernel_launch)
__device__ float Qbuf[NA * D];
__device__ float Kbuf[NB * D];
__device__ float Vbuf[NB * D];

__device__ __forceinline__ float sanitize_f(float x) {
    if (isnan(x)) return 0.0f;
    if (isinf(x)) return x > 0.0f ? 1.0f : -1.0f;
    return x;
}

// C[n, j] = sum_k sanitize(X[n,k]) * W[j,k]   (x @ W.T), X:[4096,256], W:[256,256]
__global__ void proj_kernel(const float* __restrict__ X, const float* __restrict__ W,
                            float* __restrict__ C) {
    __shared__ float Xs[16][68];
    __shared__ float Ws[16][68];
    int tx = threadIdx.x, ty = threadIdx.y;
    int tid = ty * 16 + tx;
    int row0 = blockIdx.y * 64;
    int col0 = blockIdx.x * 64;
    float acc[4][4];
#pragma unroll
    for (int i = 0; i < 4; i++)
#pragma unroll
        for (int j = 0; j < 4; j++) acc[i][j] = 0.0f;

    for (int k0 = 0; k0 < D; k0 += 16) {
#pragma unroll
        for (int i = 0; i < 4; i++) {
            int idx = tid + i * 256;
            int r = idx >> 4, kk = idx & 15;
            Xs[kk][r] = sanitize_f(X[(size_t)(row0 + r) * D + k0 + kk]);
            Ws[kk][r] = W[(size_t)(col0 + r) * D + k0 + kk];
        }
        __syncthreads();
#pragma unroll
        for (int kk = 0; kk < 16; kk++) {
            float a[4], b[4];
#pragma unroll
            for (int i = 0; i < 4; i++) a[i] = Xs[kk][ty * 4 + i];
#pragma unroll
            for (int j = 0; j < 4; j++) b[j] = Ws[kk][tx * 4 + j];
#pragma unroll
            for (int i = 0; i < 4; i++)
#pragma unroll
                for (int j = 0; j < 4; j++) acc[i][j] += a[i] * b[j];
        }
        __syncthreads();
    }
#pragma unroll
    for (int i = 0; i < 4; i++)
#pragma unroll
        for (int j = 0; j < 4; j++)
            C[(size_t)(row0 + ty * 4 + i) * D + col0 + tx * 4 + j] = acc[i][j];
}

// Fused attention: per block, 32 a-rows x 4 heads, streaming over b in tiles of 32.
// No online softmax needed: logits are clipped to [-10,10] before exp, so a single
// pass of sum(exp) is exactly equivalent to the reference's max-subtracted softmax.
__global__ __launch_bounds__(256, 1)
void attn_kernel(const int* __restrict__ mask,
                 const float* __restrict__ weight,
                 float* __restrict__ out) {
    extern __shared__ float sm[];
    float* Qs   = sm;               // [ (a*4+h)*68 + k ]  128*68
    float* Ks   = Qs + 128 * 68;    // 128*68
    float* Vs   = Ks + 128 * 68;    // 128*68
    float* Es   = Vs + 128 * 68;    // [ (a*4+h)*34 + b ]  128*34
    float* Sums = Es + 128 * 34;    // [ (a*4+h)*2 + sub ] 256
    float* Outs = Sums + 256;       // [ a*64 + j ]        2048
    // total = 3*8704 + 4352 + 256 + 2048 = 32768 floats = 131072 B

    int tid = threadIdx.x;
    int a0 = blockIdx.x * TA;

    // Stage Q tile once
    for (int idx = tid; idx < TA * D; idx += 256) {
        int aa = idx >> 8, c = idx & 255;
        Qs[((aa * 4) + (c >> 6)) * 68 + (c & 63)] = Qbuf[(size_t)(a0 + aa) * D + c];
    }

    // --- att-phase mapping: 2 threads per (a,h); each covers 16 b's of the tile
    int pair = tid >> 1;
    int aa = pair >> 2, hh = pair & 3;
    int sub = tid & 1;
    const float* qp = &Qs[(aa * 4 + hh) * 68];
    size_t mrow = (size_t)(a0 + aa) * NB;
    float lsum = 0.0f;

    // --- ctx-phase mapping: thread covers (a, 32 contiguous context cols of one head)
    int ca = tid >> 3;
    int g  = tid & 7;
    int ch = g >> 1;
    int jb = (g & 1) * 32;
    float ctx[32];
#pragma unroll
    for (int i = 0; i < 32; i++) ctx[i] = 0.0f;

    for (int b0 = 0; b0 < NB; b0 += TB) {
        __syncthreads();  // prior ctx reads done before overwriting K/V
        for (int idx = tid; idx < TB * D; idx += 256) {
            int bb = idx >> 8, c = idx & 255;
            int off = ((bb * 4) + (c >> 6)) * 68 + (c & 63);
            Ks[off] = Kbuf[(size_t)(b0 + bb) * D + c];
            Vs[off] = Vbuf[(size_t)(b0 + bb) * D + c];
        }
        __syncthreads();

        // scores: 16 dot(64) per thread, k-chunked so q is loaded once per 16 b's
        float acc[16];
#pragma unroll
        for (int i = 0; i < 16; i++) acc[i] = 0.0f;
#pragma unroll
        for (int kc = 0; kc < DK; kc += 4) {
            float4 qv = *(const float4*)(qp + kc);
#pragma unroll
            for (int bi = 0; bi < 16; bi++) {
                float4 kv = *(const float4*)(&Ks[((sub * 16 + bi) * 4 + hh) * 68 + kc]);
                acc[bi] += qv.x * kv.x + qv.y * kv.y + qv.z * kv.z + qv.w * kv.w;
            }
        }
#pragma unroll
        for (int bi = 0; bi < 16; bi++) {
            int b = sub * 16 + bi;
            int gb = b0 + b;
            float s = mask[mrow + gb] ? acc[bi] * 0.125f : -10000.0f;
            s += sanitize_f(weight[mrow + gb]);
            s = fminf(fmaxf(s, -10.0f), 10.0f);
            float e = expf(s);
            Es[(aa * 4 + hh) * 34 + b] = e;
            lsum += e;
        }
        __syncthreads();

        // context accumulate
        const float* ep = &Es[(ca * 4 + ch) * 34];
#pragma unroll 4
        for (int b = 0; b < TB; b++) {
            float e = ep[b];
            const float* vp = &Vs[(b * 4 + ch) * 68 + jb];
#pragma unroll
            for (int i = 0; i < 32; i += 4) {
                float4 vv = *(const float4*)(vp + i);
                ctx[i]     += e * vv.x;
                ctx[i + 1] += e * vv.y;
                ctx[i + 2] += e * vv.z;
                ctx[i + 3] += e * vv.w;
            }
        }
    }

    // Epilogue: combine partial sums, normalize, mean over heads
    Sums[pair * 2 + sub] = lsum;
    for (int idx = tid; idx < TA * DK; idx += 256) Outs[idx] = 0.0f;
    __syncthreads();

    float tot = Sums[(ca * 4 + ch) * 2] + Sums[(ca * 4 + ch) * 2 + 1];
    float scale = 0.25f / tot;  // 1/sumexp * mean over 4 heads
#pragma unroll
    for (int i = 0; i < 32; i++)
        atomicAdd(&Outs[ca * 64 + jb + i], ctx[i] * scale);
    __syncthreads();

    for (int idx = tid; idx < TA * DK; idx += 256) {
        int r = idx >> 6, j = idx & 63;
        out[(size_t)(a0 + r) * DK + j] = Outs[idx];
    }
    // influence = mean_h sum_b softmax = exactly 1.0
    if (tid < TA) out[(size_t)NA * DK + a0 + tid] = 1.0f;
}

extern "C" void kernel_launch(void* const* d_in, const int* in_sizes, int n_in,
                              void* d_out, int out_size) {
    const float* a_z    = (const float*)d_in[0];
    const float* bv_z   = (const float*)d_in[1];
    const int*   mask   = (const int*)d_in[2];
    const float* weight = (const float*)d_in[3];
    const float* Wq     = (const float*)d_in[4];
    const float* Wk     = (const float*)d_in[5];
    const float* Wv     = (const float*)d_in[6];
    float* out = (float*)d_out;

    float *qb, *kb, *vb;
    cudaGetSymbolAddress((void**)&qb, Qbuf);
    cudaGetSymbolAddress((void**)&kb, Kbuf);
    cudaGetSymbolAddress((void**)&vb, Vbuf);

    dim3 pg(D / 64, NA / 64), pb(16, 16);
    proj_kernel<<<pg, pb>>>(a_z, Wq, qb);
    proj_kernel<<<pg, pb>>>(bv_z, Wk, kb);
    proj_kernel<<<pg, pb>>>(bv_z, Wv, vb);

    cudaFuncSetAttribute(attn_kernel, cudaFuncAttributeMaxDynamicSharedMemorySize, 131072);
    attn_kernel<<<NA / TA, 256, 131072>>>(mask, weight, out);
}

// round 3
// speedup vs baseline: 4.1619x; 4.1619x over previous
#include <cuda_runtime.h>
#include <math.h>

#define NA 4096
#define NB 4096
#define D  256
#define H  4
#define DK 64

// Device-global scratch (no allocation in kernel_launch)
__device__ float Qbuf[NA * D];
__device__ float Kbuf[NB * D];
__device__ float Vbuf[NB * D];
__device__ float Ebuf[(size_t)H * NA * NB];   // 268MB: exp(clipped logits), fp32
__device__ float CtxPart[4][NA * D];          // k-split partial contexts [s][a][h*64+j]
__device__ float SumPart[32][NA * H];         // per-btile row sums [bt][a*4+h]
__device__ float Sums[NA * H];

__device__ __forceinline__ float sanitize_f(float x) {
    if (isnan(x)) return 0.0f;
    if (isinf(x)) return x > 0.0f ? 1.0f : -1.0f;
    return x;
}

// ---------------- projections: C[n,j] = sum_k sanitize(X[n,k]) * W[j,k] ----------------
__global__ void proj_kernel(const float* __restrict__ X, const float* __restrict__ W,
                            float* __restrict__ C) {
    __shared__ float Xs[16][68];
    __shared__ float Ws[16][68];
    int tx = threadIdx.x, ty = threadIdx.y;
    int tid = ty * 16 + tx;
    int row0 = blockIdx.y * 64;
    int col0 = blockIdx.x * 64;
    float acc[4][4];
#pragma unroll
    for (int i = 0; i < 4; i++)
#pragma unroll
        for (int j = 0; j < 4; j++) acc[i][j] = 0.0f;

    for (int k0 = 0; k0 < D; k0 += 16) {
#pragma unroll
        for (int i = 0; i < 4; i++) {
            int idx = tid + i * 256;
            int r = idx >> 4, kk = idx & 15;
            Xs[kk][r] = sanitize_f(X[(size_t)(row0 + r) * D + k0 + kk]);
            Ws[kk][r] = W[(size_t)(col0 + r) * D + k0 + kk];
        }
        __syncthreads();
#pragma unroll
        for (int kk = 0; kk < 16; kk++) {
            float a[4], b[4];
#pragma unroll
            for (int i = 0; i < 4; i++) a[i] = Xs[kk][ty * 4 + i];
#pragma unroll
            for (int j = 0; j < 4; j++) b[j] = Ws[kk][tx * 4 + j];
#pragma unroll
            for (int i = 0; i < 4; i++)
#pragma unroll
                for (int j = 0; j < 4; j++) acc[i][j] += a[i] * b[j];
        }
        __syncthreads();
    }
#pragma unroll
    for (int i = 0; i < 4; i++)
#pragma unroll
        for (int j = 0; j < 4; j++)
            C[(size_t)(row0 + ty * 4 + i) * D + col0 + tx * 4 + j] = acc[i][j];
}

// ---------------- scores: E[h][a][b] = exp(clip(mask? qk/8 : -1e4) + w), row sums ----------------
// Block: 128a x 128b tile of one head. 256 threads, 8x8 per thread. grid.x = bt*4+h (h fastest
// for L2 reuse of mask/weight across heads), grid.y = at.
__global__ __launch_bounds__(256, 2)
void score_kernel(const int* __restrict__ mask, const float* __restrict__ weight) {
    extern __shared__ float sm[];
    float* Qs = sm;             // [64][132] transposed: Qs[kk][m]
    float* Ks = sm + 64 * 132;  // [64][132]
    int bt = blockIdx.x >> 2, h = blockIdx.x & 3, at = blockIdx.y;
    int a0 = at * 128, b0 = bt * 128;
    int tid = threadIdx.x;
    int tx = tid & 15, ty = tid >> 4;

    const float4* Q4 = (const float4*)Qbuf;
    const float4* K4 = (const float4*)Kbuf;
#pragma unroll
    for (int it = 0; it < 8; it++) {
        int idx = tid + it * 256;         // 0..2047
        int r = idx >> 4, c4 = idx & 15;  // row, float4-chunk of the 64 k's
        float4 q = Q4[(size_t)(a0 + r) * 64 + h * 16 + c4];
        float4 k = K4[(size_t)(b0 + r) * 64 + h * 16 + c4];
        int kk = c4 * 4;
        Qs[(kk + 0) * 132 + r] = q.x; Qs[(kk + 1) * 132 + r] = q.y;
        Qs[(kk + 2) * 132 + r] = q.z; Qs[(kk + 3) * 132 + r] = q.w;
        Ks[(kk + 0) * 132 + r] = k.x; Ks[(kk + 1) * 132 + r] = k.y;
        Ks[(kk + 2) * 132 + r] = k.z; Ks[(kk + 3) * 132 + r] = k.w;
    }
    __syncthreads();

    float acc[8][8];
#pragma unroll
    for (int i = 0; i < 8; i++)
#pragma unroll
        for (int j = 0; j < 8; j++) acc[i][j] = 0.0f;

#pragma unroll 8
    for (int kk = 0; kk < 64; kk++) {
        float af[8], bf[8];
        *(float4*)(af)     = *(const float4*)&Qs[kk * 132 + ty * 8];
        *(float4*)(af + 4) = *(const float4*)&Qs[kk * 132 + ty * 8 + 4];
        *(float4*)(bf)     = *(const float4*)&Ks[kk * 132 + tx * 8];
        *(float4*)(bf + 4) = *(const float4*)&Ks[kk * 132 + tx * 8 + 4];
#pragma unroll
        for (int i = 0; i < 8; i++)
#pragma unroll
            for (int j = 0; j < 8; j++) acc[i][j] += af[i] * bf[j];
    }

    // epilogue: mask/weight/clip/exp, write E, reduce row sums
    float lsum[8];
#pragma unroll
    for (int i = 0; i < 8; i++) {
        int a = a0 + ty * 8 + i;
        size_t base = (size_t)a * NB + b0 + tx * 8;
        int4   m0 = *(const int4*)(mask + base);
        int4   m1 = *(const int4*)(mask + base + 4);
        float4 w0 = *(const float4*)(weight + base);
        float4 w1 = *(const float4*)(weight + base + 4);
        int   mi[8] = {m0.x, m0.y, m0.z, m0.w, m1.x, m1.y, m1.z, m1.w};
        float wi[8] = {w0.x, w0.y, w0.z, w0.w, w1.x, w1.y, w1.z, w1.w};
        float e[8];
        float rs = 0.0f;
#pragma unroll
        for (int j = 0; j < 8; j++) {
            float s = mi[j] ? acc[i][j] * 0.125f : -10000.0f;
            s += sanitize_f(wi[j]);
            s = fminf(fmaxf(s, -10.0f), 10.0f);
            e[j] = __expf(s);
            rs += e[j];
        }
        lsum[i] = rs;
        float* ep = Ebuf + ((size_t)(h * NA + a)) * NB + b0 + tx * 8;
        *(float4*)(ep)     = make_float4(e[0], e[1], e[2], e[3]);
        *(float4*)(ep + 4) = make_float4(e[4], e[5], e[6], e[7]);
    }
#pragma unroll
    for (int i = 0; i < 8; i++) {
        lsum[i] += __shfl_xor_sync(0xffffffffu, lsum[i], 1, 16);
        lsum[i] += __shfl_xor_sync(0xffffffffu, lsum[i], 2, 16);
        lsum[i] += __shfl_xor_sync(0xffffffffu, lsum[i], 4, 16);
        lsum[i] += __shfl_xor_sync(0xffffffffu, lsum[i], 8, 16);
    }
    if (tx == 0) {
#pragma unroll
        for (int i = 0; i < 8; i++)
            SumPart[bt][(a0 + ty * 8 + i) * 4 + h] = lsum[i];
    }
}

// ---------------- context: CtxPart[s][a][h*64+n] = sum_{b in split s} E[h][a][b] V[b][h*64+n] ----------------
// Block: 128a x 64n per (at, h, split). K chunk = 1024, tiled by 64.
__global__ __launch_bounds__(256, 3)
void ctx_kernel() {
    extern __shared__ float sm[];
    float* Es = sm;             // [64][132] transposed: Es[kk][m]
    float* Vs = sm + 64 * 132;  // [64][68]:  Vs[kk][n]
    int at = blockIdx.x, h = blockIdx.y, s = blockIdx.z;
    int a0 = at * 128;
    int tid = threadIdx.x;
    int tx = tid & 15, ty = tid >> 4;

    const float4* V4 = (const float4*)Vbuf;
    float acc[8][4];
#pragma unroll
    for (int i = 0; i < 8; i++)
#pragma unroll
        for (int j = 0; j < 4; j++) acc[i][j] = 0.0f;

    for (int t = 0; t < 16; t++) {
        int k0 = s * 1024 + t * 64;
        __syncthreads();
#pragma unroll
        for (int it = 0; it < 8; it++) {
            int idx = tid + it * 256;
            int r = idx >> 4, c4 = idx & 15;
            float4 e = *(const float4*)&Ebuf[((size_t)(h * NA + a0 + r)) * NB + k0 + c4 * 4];
            int kk = c4 * 4;
            Es[(kk + 0) * 132 + r] = e.x; Es[(kk + 1) * 132 + r] = e.y;
            Es[(kk + 2) * 132 + r] = e.z; Es[(kk + 3) * 132 + r] = e.w;
        }
#pragma unroll
        for (int it = 0; it < 4; it++) {
            int idx = tid + it * 256;     // 0..1023
            int r = idx >> 4, c4 = idx & 15;
            float4 v = V4[(size_t)(k0 + r) * 64 + h * 16 + c4];
            *(float4*)&Vs[r * 68 + c4 * 4] = v;
        }
        __syncthreads();

#pragma unroll 8
        for (int kk = 0; kk < 64; kk++) {
            float af[8];
            *(float4*)(af)     = *(const float4*)&Es[kk * 132 + ty * 8];
            *(float4*)(af + 4) = *(const float4*)&Es[kk * 132 + ty * 8 + 4];
            float4 bv = *(const float4*)&Vs[kk * 68 + tx * 4];
#pragma unroll
            for (int i = 0; i < 8; i++) {
                acc[i][0] += af[i] * bv.x;
                acc[i][1] += af[i] * bv.y;
                acc[i][2] += af[i] * bv.z;
                acc[i][3] += af[i] * bv.w;
            }
        }
    }
#pragma unroll
    for (int i = 0; i < 8; i++) {
        float* cp = &CtxPart[s][(a0 + ty * 8 + i) * 256 + h * 64 + tx * 4];
        *(float4*)cp = make_float4(acc[i][0], acc[i][1], acc[i][2], acc[i][3]);
    }
}

// ---------------- reductions ----------------
__global__ void sum_kernel() {
    int idx = blockIdx.x * 256 + threadIdx.x;  // 16384 = NA*H
    float s = 0.0f;
#pragma unroll
    for (int bt = 0; bt < 32; bt++) s += SumPart[bt][idx];
    Sums[idx] = s;
}

__global__ void combine_kernel(float* __restrict__ out) {
    int idx = blockIdx.x * 256 + threadIdx.x;  // NA*DK
    int a = idx >> 6, j = idx & 63;
    float v = 0.0f;
#pragma unroll
    for (int h = 0; h < 4; h++) {
        float c = 0.0f;
#pragma unroll
        for (int s = 0; s < 4; s++) c += CtxPart[s][a * 256 + h * 64 + j];
        v += c / Sums[a * 4 + h];
    }
    out[idx] = 0.25f * v;
    if (j == 0) out[NA * DK + a] = 1.0f;  // influence = mean_h sum_b softmax = 1
}

extern "C" void kernel_launch(void* const* d_in, const int* in_sizes, int n_in,
                              void* d_out, int out_size) {
    const float* a_z    = (const float*)d_in[0];
    const float* bv_z   = (const float*)d_in[1];
    const int*   mask   = (const int*)d_in[2];
    const float* weight = (const float*)d_in[3];
    const float* Wq     = (const float*)d_in[4];
    const float* Wk     = (const float*)d_in[5];
    const float* Wv     = (const float*)d_in[6];
    float* out = (float*)d_out;

    float *qb, *kb, *vb;
    cudaGetSymbolAddress((void**)&qb, Qbuf);
    cudaGetSymbolAddress((void**)&kb, Kbuf);
    cudaGetSymbolAddress((void**)&vb, Vbuf);

    dim3 pg(D / 64, NA / 64), pb(16, 16);
    proj_kernel<<<pg, pb>>>(a_z, Wq, qb);
    proj_kernel<<<pg, pb>>>(bv_z, Wk, kb);
    proj_kernel<<<pg, pb>>>(bv_z, Wv, vb);

    int score_smem = 2 * 64 * 132 * 4;  // 67584
    int ctx_smem   = (64 * 132 + 64 * 68) * 4;  // 51200
    cudaFuncSetAttribute(score_kernel, cudaFuncAttributeMaxDynamicSharedMemorySize, score_smem);
    cudaFuncSetAttribute(ctx_kernel,   cudaFuncAttributeMaxDynamicSharedMemorySize, ctx_smem);

    score_kernel<<<dim3(128, 32), 256, score_smem>>>(mask, weight);
    ctx_kernel<<<dim3(32, 4, 4), 256, ctx_smem>>>();
    sum_kernel<<<64, 256>>>();
    combine_kernel<<<NA * DK / 256, 256>>>(out);
}

// round 6
// speedup vs baseline: 5.8077x; 1.3954x over previous
#include <cuda_runtime.h>
#include <cuda_bf16.h>
#include <math.h>
#include <stdint.h>

#define NA 4096
#define NB 4096
#define D  256
#define H  4
#define DK 64

// ---------------- device-global scratch ----------------
__device__ float Qbuf[NA * D];
__device__ float Kbuf[NB * D];
__device__ float Vbuf[NB * D];
__device__ __nv_bfloat16 QhB[NA * D], QlB[NA * D];
__device__ __nv_bfloat16 KhB[NB * D], KlB[NB * D];
__device__ __nv_bfloat16 VtH[D * NB], VtL[D * NB];   // [h*64+j][b]
__device__ __nv_bfloat16 EH[(size_t)H * NA * NB];    // 134MB
__device__ __nv_bfloat16 EL[(size_t)H * NA * NB];    // 134MB
__device__ float CtxPart[2][NA * D];
__device__ float SumPart[32][NA * H];
__device__ float SumsG[NA * H];

__device__ __forceinline__ float sanitize_f(float x) {
    if (isnan(x)) return 0.0f;
    if (isinf(x)) return x > 0.0f ? 1.0f : -1.0f;
    return x;
}

// ---------------- generic PTX helpers (sm_80+ features only) ----------------
__device__ __forceinline__ uint32_t smem_u32(const void* p) {
    uint32_t a;
    asm("{ .reg .u64 t; cvta.to.shared.u64 t, %1; cvt.u32.u64 %0, t; }" : "=r"(a) : "l"(p));
    return a;
}
__device__ __forceinline__ void ldmx4(uint32_t* r, uint32_t addr) {
    asm volatile("ldmatrix.sync.aligned.m8n8.x4.shared.b16 {%0,%1,%2,%3}, [%4];"
                 : "=r"(r[0]), "=r"(r[1]), "=r"(r[2]), "=r"(r[3]) : "r"(addr));
}
__device__ __forceinline__ void ldmx2(uint32_t* r, uint32_t addr) {
    asm volatile("ldmatrix.sync.aligned.m8n8.x2.shared.b16 {%0,%1}, [%2];"
                 : "=r"(r[0]), "=r"(r[1]) : "r"(addr));
}
__device__ __forceinline__ void mma16816(float* c, const uint32_t* a, const uint32_t* b) {
    asm volatile(
        "mma.sync.aligned.m16n8k16.row.col.f32.bf16.bf16.f32 "
        "{%0,%1,%2,%3}, {%4,%5,%6,%7}, {%8,%9}, {%0,%1,%2,%3};"
        : "+f"(c[0]), "+f"(c[1]), "+f"(c[2]), "+f"(c[3])
        : "r"(a[0]), "r"(a[1]), "r"(a[2]), "r"(a[3]), "r"(b[0]), "r"(b[1]));
}
__device__ __forceinline__ void cp16(uint32_t dst, const void* src) {
    asm volatile("cp.async.cg.shared.global [%0], [%1], 16;" :: "r"(dst), "l"(src));
}
#define CP_COMMIT() asm volatile("cp.async.commit_group;" ::: "memory")
#define CP_WAIT0()  asm volatile("cp.async.wait_group 0;" ::: "memory")
#define CP_WAIT1()  asm volatile("cp.async.wait_group 1;" ::: "memory")

// ---------------- projections (fp32) ----------------
__global__ void proj_kernel(const float* __restrict__ X, const float* __restrict__ W,
                            float* __restrict__ C) {
    __shared__ float Xs[16][68];
    __shared__ float Ws[16][68];
    int tx = threadIdx.x, ty = threadIdx.y;
    int tid = ty * 16 + tx;
    int row0 = blockIdx.y * 64;
    int col0 = blockIdx.x * 64;
    float acc[4][4];
#pragma unroll
    for (int i = 0; i < 4; i++)
#pragma unroll
        for (int j = 0; j < 4; j++) acc[i][j] = 0.0f;

    for (int k0 = 0; k0 < D; k0 += 16) {
#pragma unroll
        for (int i = 0; i < 4; i++) {
            int idx = tid + i * 256;
            int r = idx >> 4, kk = idx & 15;
            Xs[kk][r] = sanitize_f(X[(size_t)(row0 + r) * D + k0 + kk]);
            Ws[kk][r] = W[(size_t)(col0 + r) * D + k0 + kk];
        }
        __syncthreads();
#pragma unroll
        for (int kk = 0; kk < 16; kk++) {
            float a[4], b[4];
#pragma unroll
            for (int i = 0; i < 4; i++) a[i] = Xs[kk][ty * 4 + i];
#pragma unroll
            for (int j = 0; j < 4; j++) b[j] = Ws[kk][tx * 4 + j];
#pragma unroll
            for (int i = 0; i < 4; i++)
#pragma unroll
                for (int j = 0; j < 4; j++) acc[i][j] += a[i] * b[j];
        }
        __syncthreads();
    }
#pragma unroll
    for (int i = 0; i < 4; i++)
#pragma unroll
        for (int j = 0; j < 4; j++)
            C[(size_t)(row0 + ty * 4 + i) * D + col0 + tx * 4 + j] = acc[i][j];
}

// ---------------- split fp32 -> bf16 hi/lo (+ V transpose) ----------------
__global__ void split_kernel() {
    int i = blockIdx.x * 256 + threadIdx.x;
    float q = Qbuf[i];
    __nv_bfloat16 qh = __float2bfloat16_rn(q);
    QhB[i] = qh;
    QlB[i] = __float2bfloat16_rn(q - __bfloat162float(qh));
    float k = Kbuf[i];
    __nv_bfloat16 kh = __float2bfloat16_rn(k);
    KhB[i] = kh;
    KlB[i] = __float2bfloat16_rn(k - __bfloat162float(kh));
    float v = Vbuf[i];
    __nv_bfloat16 vh = __float2bfloat16_rn(v);
    int n = i >> 8, c = i & 255;
    VtH[c * NB + n] = vh;
    VtL[c * NB + n] = __float2bfloat16_rn(v - __bfloat162float(vh));
}

// ---------------- scores via mma.sync: 128a x 128b per (at, bt, h) ----------------
// 8 warps: warp_m = wid>>2 (64 rows), warp_n = wid&3 (32 cols). 3-pass bf16 hi/lo.
#define QST 72   // smem row stride (bf16 elems): 144B -> conflict-free ldmatrix
__global__ __launch_bounds__(256, 2)
void score_mma(const int* __restrict__ mask, const float* __restrict__ weight) {
    extern __shared__ char sm[];
    __nv_bfloat16* Qh = (__nv_bfloat16*)sm;      // [128][72]
    __nv_bfloat16* Ql = Qh + 128 * QST;
    __nv_bfloat16* Kh = Ql + 128 * QST;
    __nv_bfloat16* Kl = Kh + 128 * QST;
    float* Sred = (float*)(Kl + 128 * QST);      // [4][128]

    int tid = threadIdx.x, wid = tid >> 5, lane = tid & 31;
    int at = blockIdx.y, bt = blockIdx.x >> 2, h = blockIdx.x & 3;
    int a0 = at * 128, b0 = bt * 128;

    const uint4* qh4 = (const uint4*)QhB;
    const uint4* ql4 = (const uint4*)QlB;
    const uint4* kh4 = (const uint4*)KhB;
    const uint4* kl4 = (const uint4*)KlB;
#pragma unroll
    for (int it = 0; it < 4; it++) {
        int idx = tid + it * 256;          // 0..1023
        int r = idx >> 3, c = idx & 7;     // row, 8-bf16 chunk of the 64 k's
        int qi = (a0 + r) * 32 + h * 8 + c;
        int ki = (b0 + r) * 32 + h * 8 + c;
        *(uint4*)(Qh + r * QST + c * 8) = qh4[qi];
        *(uint4*)(Ql + r * QST + c * 8) = ql4[qi];
        *(uint4*)(Kh + r * QST + c * 8) = kh4[ki];
        *(uint4*)(Kl + r * QST + c * 8) = kl4[ki];
    }
    __syncthreads();

    int wm = (wid >> 2) * 64, wn = (wid & 3) * 32;
    float acc[4][4][4];
#pragma unroll
    for (int i = 0; i < 4; i++)
#pragma unroll
        for (int j = 0; j < 4; j++)
#pragma unroll
            for (int t = 0; t < 4; t++) acc[i][j][t] = 0.0f;

    uint32_t aB[3] = {smem_u32(Qh), smem_u32(Ql), smem_u32(Qh)};
    uint32_t bB[3] = {smem_u32(Kh), smem_u32(Kh), smem_u32(Kl)};
    int arow = lane & 15, ahalf = lane >> 4;
    int brow = lane & 7,  bhalf = (lane >> 3) & 1;

#pragma unroll
    for (int p = 0; p < 3; p++) {
#pragma unroll
        for (int k0 = 0; k0 < 64; k0 += 16) {
            uint32_t af[4][4], bf[4][2];
#pragma unroll
            for (int mf = 0; mf < 4; mf++)
                ldmx4(af[mf], aB[p] + ((wm + mf * 16 + arow) * QST + k0 + ahalf * 8) * 2);
#pragma unroll
            for (int nf = 0; nf < 4; nf++)
                ldmx2(bf[nf], bB[p] + ((wn + nf * 8 + brow) * QST + k0 + bhalf * 8) * 2);
#pragma unroll
            for (int mf = 0; mf < 4; mf++)
#pragma unroll
                for (int nf = 0; nf < 4; nf++) mma16816(acc[mf][nf], af[mf], bf[nf]);
        }
    }

    // epilogue
    int qr = lane >> 2, qc = (lane & 3) * 2;
#pragma unroll
    for (int mf = 0; mf < 4; mf++) {
#pragma unroll
        for (int hf = 0; hf < 2; hf++) {
            int a = a0 + wm + mf * 16 + hf * 8 + qr;
            size_t base  = (size_t)a * NB + b0 + wn;
            size_t ebase = ((size_t)h * NA + a) * NB + b0 + wn;
            float rs = 0.0f;
#pragma unroll
            for (int nf = 0; nf < 4; nf++) {
                int2   m = *(const int2*)(mask + base + nf * 8 + qc);
                float2 w = *(const float2*)(weight + base + nf * 8 + qc);
                float d0 = acc[mf][nf][hf * 2 + 0];
                float d1 = acc[mf][nf][hf * 2 + 1];
                float s0 = m.x ? d0 * 0.125f : -10000.0f;
                float s1 = m.y ? d1 * 0.125f : -10000.0f;
                s0 += sanitize_f(w.x);
                s1 += sanitize_f(w.y);
                s0 = fminf(fmaxf(s0, -10.0f), 10.0f);
                s1 = fminf(fmaxf(s1, -10.0f), 10.0f);
                float e0 = __expf(s0), e1 = __expf(s1);
                rs += e0 + e1;
                __nv_bfloat16 h0 = __float2bfloat16_rn(e0);
                __nv_bfloat16 h1 = __float2bfloat16_rn(e1);
                __nv_bfloat162 hv; hv.x = h0; hv.y = h1;
                __nv_bfloat162 lv;
                lv.x = __float2bfloat16_rn(e0 - __bfloat162float(h0));
                lv.y = __float2bfloat16_rn(e1 - __bfloat162float(h1));
                *(__nv_bfloat162*)(EH + ebase + nf * 8 + qc) = hv;
                *(__nv_bfloat162*)(EL + ebase + nf * 8 + qc) = lv;
            }
            rs += __shfl_xor_sync(0xffffffffu, rs, 1);
            rs += __shfl_xor_sync(0xffffffffu, rs, 2);
            if ((lane & 3) == 0)
                Sred[(wid & 3) * 128 + wm + mf * 16 + hf * 8 + qr] = rs;
        }
    }
    __syncthreads();
    if (tid < 128)
        SumPart[bt][(a0 + tid) * 4 + h] =
            Sred[tid] + Sred[128 + tid] + Sred[256 + tid] + Sred[384 + tid];
}

// ---------------- context via mma.sync: 128a x 64j per (at, h, s) ----------------
// K = 2048 per CTA in chunks of 32, double-buffered cp.async.
#define CST 40   // smem row stride (bf16): 80B -> conflict-free ldmatrix
#define STAGE_ELEMS (128 * CST * 2 + 64 * CST * 2)   // Eh,El,Vh,Vl = 15360
__global__ __launch_bounds__(256, 2)
void ctx_mma() {
    extern __shared__ char sm[];
    __nv_bfloat16* S = (__nv_bfloat16*)sm;
    int tid = threadIdx.x, wid = tid >> 5, lane = tid & 31;
    int at = blockIdx.x, h = blockIdx.y, sp = blockIdx.z;
    int a0 = at * 128, kbase = sp * 2048;
    int wm = (wid >> 1) * 32, wn = (wid & 1) * 32;

    float acc[2][4][4];
#pragma unroll
    for (int i = 0; i < 2; i++)
#pragma unroll
        for (int j = 0; j < 4; j++)
#pragma unroll
            for (int t = 0; t < 4; t++) acc[i][j][t] = 0.0f;

    const int OEL = 128 * CST, OVH = 2 * 128 * CST, OVL = 2 * 128 * CST + 64 * CST;

    // stage loader
    auto stage_load = [&](int st, int k0) {
        uint32_t sb = smem_u32(S + st * STAGE_ELEMS);
#pragma unroll
        for (int it = 0; it < 2; it++) {
            int idx = tid + it * 256;      // 0..511
            int r = idx >> 2, c = idx & 3;
            uint32_t d = sb + (r * CST + c * 8) * 2;
            size_t g = ((size_t)h * NA + a0 + r) * NB + k0 + c * 8;
            cp16(d, EH + g);
            cp16(d + OEL * 2, EL + g);
        }
        {
            int r = tid >> 2, c = tid & 3;  // 0..63 rows
            uint32_t d = sb + (OVH + r * CST + c * 8) * 2;
            size_t g = (size_t)(h * 64 + r) * NB + k0 + c * 8;
            cp16(d, VtH + g);
            cp16(d + (OVL - OVH) * 2, VtL + g);
        }
        CP_COMMIT();
    };

    stage_load(0, kbase);
    int arow = lane & 15, ahalf = lane >> 4;
    int brow = lane & 7,  bhalf = (lane >> 3) & 1;

    for (int c = 0; c < 64; c++) {
        int st = c & 1;
        if (c + 1 < 64) { stage_load(st ^ 1, kbase + (c + 1) * 32); CP_WAIT1(); }
        else           { CP_WAIT0(); }
        __syncthreads();

        uint32_t eb = smem_u32(S + st * STAGE_ELEMS);
        uint32_t aB[3] = {eb, eb + OEL * 2, eb};
        uint32_t bB[3] = {eb + OVH * 2, eb + OVH * 2, eb + OVL * 2};
#pragma unroll
        for (int p = 0; p < 3; p++) {
#pragma unroll
            for (int k0 = 0; k0 < 32; k0 += 16) {
                uint32_t af[2][4], bf[4][2];
#pragma unroll
                for (int mf = 0; mf < 2; mf++)
                    ldmx4(af[mf], aB[p] + ((wm + mf * 16 + arow) * CST + k0 + ahalf * 8) * 2);
#pragma unroll
                for (int nf = 0; nf < 4; nf++)
                    ldmx2(bf[nf], bB[p] + ((wn + nf * 8 + brow) * CST + k0 + bhalf * 8) * 2);
#pragma unroll
                for (int mf = 0; mf < 2; mf++)
#pragma unroll
                    for (int nf = 0; nf < 4; nf++) mma16816(acc[mf][nf], af[mf], bf[nf]);
            }
        }
        __syncthreads();
    }

    int qr = lane >> 2, qc = (lane & 3) * 2;
#pragma unroll
    for (int mf = 0; mf < 2; mf++) {
#pragma unroll
        for (int hf = 0; hf < 2; hf++) {
            int a = a0 + wm + mf * 16 + hf * 8 + qr;
            float* cp = &CtxPart[sp][(size_t)a * 256 + h * 64 + wn];
#pragma unroll
            for (int nf = 0; nf < 4; nf++) {
                float2 v;
                v.x = acc[mf][nf][hf * 2 + 0];
                v.y = acc[mf][nf][hf * 2 + 1];
                *(float2*)(cp + nf * 8 + qc) = v;
            }
        }
    }
}

// ---------------- reductions ----------------
__global__ void sum_kernel() {
    int idx = blockIdx.x * 256 + threadIdx.x;  // NA*H
    float s = 0.0f;
#pragma unroll
    for (int bt = 0; bt < 32; bt++) s += SumPart[bt][idx];
    SumsG[idx] = s;
}

__global__ void combine_kernel(float* __restrict__ out) {
    int idx = blockIdx.x * 256 + threadIdx.x;  // NA*DK
    int a = idx >> 6, j = idx & 63;
    float v = 0.0f;
#pragma unroll
    for (int h = 0; h < 4; h++) {
        float c = CtxPart[0][(size_t)a * 256 + h * 64 + j] + CtxPart[1][(size_t)a * 256 + h * 64 + j];
        v += c / SumsG[a * 4 + h];
    }
    out[idx] = 0.25f * v;
    if (j == 0) out[NA * DK + a] = 1.0f;  // influence == 1 exactly
}

extern "C" void kernel_launch(void* const* d_in, const int* in_sizes, int n_in,
                              void* d_out, int out_size) {
    const float* a_z    = (const float*)d_in[0];
    const float* bv_z   = (const float*)d_in[1];
    const int*   mask   = (const int*)d_in[2];
    const float* weight = (const float*)d_in[3];
    const float* Wq     = (const float*)d_in[4];
    const float* Wk     = (const float*)d_in[5];
    const float* Wv     = (const float*)d_in[6];
    float* out = (float*)d_out;

    float *qb, *kb, *vb;
    cudaGetSymbolAddress((void**)&qb, Qbuf);
    cudaGetSymbolAddress((void**)&kb, Kbuf);
    cudaGetSymbolAddress((void**)&vb, Vbuf);

    dim3 pg(D / 64, NA / 64), pb(16, 16);
    proj_kernel<<<pg, pb>>>(a_z, Wq, qb);
    proj_kernel<<<pg, pb>>>(bv_z, Wk, kb);
    proj_kernel<<<pg, pb>>>(bv_z, Wv, vb);

    split_kernel<<<NA * D / 256, 256>>>();

    int score_smem = 4 * 128 * QST * 2 + 4 * 128 * 4;    // 73728 + 2048 = 75776
    int ctx_smem   = 2 * STAGE_ELEMS * 2;                // 61440
    cudaFuncSetAttribute(score_mma, cudaFuncAttributeMaxDynamicSharedMemorySize, score_smem);
    cudaFuncSetAttribute(ctx_mma,   cudaFuncAttributeMaxDynamicSharedMemorySize, ctx_smem);

    score_mma<<<dim3(128, 32), 256, score_smem>>>(mask, weight);
    sum_kernel<<<NA * H / 256, 256>>>();
    ctx_mma<<<dim3(32, 4, 2), 256, ctx_smem>>>();
    combine_kernel<<<NA * DK / 256, 256>>>(out);
}

// round 7
// speedup vs baseline: 7.2966x; 1.2564x over previous
#include <cuda_runtime.h>
#include <cuda_bf16.h>
#include <math.h>
#include <stdint.h>

#define NA 4096
#define NB 4096
#define D  256
#define H  4
#define DK 64
#define QST 72    // Q/K smem row stride (bf16)
#define VST 136   // Vt/P smem row stride (bf16)

// ---------------- device-global scratch ----------------
__device__ __nv_bfloat16 AhB[NA * D], AlB[NA * D];
__device__ __nv_bfloat16 BhB[NB * D], BlB[NB * D];
__device__ __nv_bfloat16 WHb[3][D * D], WLb[3][D * D];
__device__ __nv_bfloat16 QhB[NA * D], QlB[NA * D];
__device__ __nv_bfloat16 KhB[NB * D], KlB[NB * D];
__device__ __nv_bfloat16 VtH[D * NB], VtL[D * NB];   // [h*64+j][b]
__device__ float CtxHd[H][NA * DK];

__device__ __forceinline__ float sanitize_f(float x) {
    if (isnan(x)) return 0.0f;
    if (isinf(x)) return x > 0.0f ? 1.0f : -1.0f;
    return x;
}

// ---------------- generic PTX helpers (sm_80+ only) ----------------
__device__ __forceinline__ uint32_t smem_u32(const void* p) {
    uint32_t a;
    asm("{ .reg .u64 t; cvta.to.shared.u64 t, %1; cvt.u32.u64 %0, t; }" : "=r"(a) : "l"(p));
    return a;
}
__device__ __forceinline__ void ldmx4(uint32_t* r, uint32_t addr) {
    asm volatile("ldmatrix.sync.aligned.m8n8.x4.shared.b16 {%0,%1,%2,%3}, [%4];"
                 : "=r"(r[0]), "=r"(r[1]), "=r"(r[2]), "=r"(r[3]) : "r"(addr));
}
__device__ __forceinline__ void ldmx2(uint32_t* r, uint32_t addr) {
    asm volatile("ldmatrix.sync.aligned.m8n8.x2.shared.b16 {%0,%1}, [%2];"
                 : "=r"(r[0]), "=r"(r[1]) : "r"(addr));
}
__device__ __forceinline__ void mma16816(float* c, const uint32_t* a, const uint32_t* b) {
    asm volatile(
        "mma.sync.aligned.m16n8k16.row.col.f32.bf16.bf16.f32 "
        "{%0,%1,%2,%3}, {%4,%5,%6,%7}, {%8,%9}, {%0,%1,%2,%3};"
        : "+f"(c[0]), "+f"(c[1]), "+f"(c[2]), "+f"(c[3])
        : "r"(a[0]), "r"(a[1]), "r"(a[2]), "r"(a[3]), "r"(b[0]), "r"(b[1]));
}
__device__ __forceinline__ void cp16(uint32_t dst, const void* src) {
    asm volatile("cp.async.cg.shared.global [%0], [%1], 16;" :: "r"(dst), "l"(src));
}
#define CP_COMMIT() asm volatile("cp.async.commit_group;" ::: "memory")
#define CP_WAIT0()  asm volatile("cp.async.wait_group 0;" ::: "memory")
#define CP_WAIT1()  asm volatile("cp.async.wait_group 1;" ::: "memory")
#define CP_WAIT2()  asm volatile("cp.async.wait_group 2;" ::: "memory")

__device__ __forceinline__ uint32_t pack2bf(float a, float b) {
    __nv_bfloat162 t;
    t.x = __float2bfloat16_rn(a);
    t.y = __float2bfloat16_rn(b);
    return *(uint32_t*)&t;
}

// ---------------- split fp32 -> bf16 hi/lo ----------------
__global__ void split_kernel(const float* __restrict__ src, __nv_bfloat16* __restrict__ hi,
                             __nv_bfloat16* __restrict__ lo, int n, int dosan) {
    int i = blockIdx.x * 256 + threadIdx.x;
    if (i >= n) return;
    float x = src[i];
    if (dosan) x = sanitize_f(x);
    __nv_bfloat16 xh = __float2bfloat16_rn(x);
    hi[i] = xh;
    lo[i] = __float2bfloat16_rn(x - __bfloat162float(xh));
}

// ---------------- projection via mma.sync, 3-pass bf16 ----------------
// OUT[4096,256] = X @ W^T. MODE 0: write Oh/Ol in [n][256] layout. MODE 1: write transposed Vt[j][n].
template <int MODE>
__global__ __launch_bounds__(256)
void proj_mma(const __nv_bfloat16* __restrict__ Xh, const __nv_bfloat16* __restrict__ Xl,
              const __nv_bfloat16* __restrict__ Wh, const __nv_bfloat16* __restrict__ Wl,
              __nv_bfloat16* __restrict__ Oh, __nv_bfloat16* __restrict__ Ol) {
    extern __shared__ char sm[];
    const int OXH = 0, OXL = 128 * QST * 2, OWH = 2 * 128 * QST * 2, OWL = OWH + 64 * QST * 2;
    uint32_t sb = smem_u32(sm);
    int tid = threadIdx.x, wid = tid >> 5, lane = tid & 31;
    int m0 = blockIdx.x * 128, n0 = blockIdx.y * 64;
    int wm = (wid >> 2) * 64, wn = (wid & 3) * 16;
    int arow = lane & 15, ahalf = lane >> 4;
    int brow = lane & 7, bhalf = (lane >> 3) & 1;

    float acc[4][2][4];
#pragma unroll
    for (int i = 0; i < 4; i++)
#pragma unroll
        for (int j = 0; j < 2; j++)
#pragma unroll
            for (int t = 0; t < 4; t++) acc[i][j][t] = 0.0f;

    for (int kc = 0; kc < 4; kc++) {
        int k0g = kc * 64;
        __syncthreads();
#pragma unroll
        for (int it = 0; it < 4; it++) {
            int idx = tid + it * 256;          // 0..1023
            int r = idx >> 3, c = idx & 7;
            *(uint4*)(sm + OXH + (r * QST + c * 8) * 2) = *(const uint4*)(Xh + (size_t)(m0 + r) * 256 + k0g + c * 8);
            *(uint4*)(sm + OXL + (r * QST + c * 8) * 2) = *(const uint4*)(Xl + (size_t)(m0 + r) * 256 + k0g + c * 8);
        }
#pragma unroll
        for (int it = 0; it < 2; it++) {
            int idx = tid + it * 256;          // 0..511
            int r = idx >> 3, c = idx & 7;
            *(uint4*)(sm + OWH + (r * QST + c * 8) * 2) = *(const uint4*)(Wh + (size_t)(n0 + r) * 256 + k0g + c * 8);
            *(uint4*)(sm + OWL + (r * QST + c * 8) * 2) = *(const uint4*)(Wl + (size_t)(n0 + r) * 256 + k0g + c * 8);
        }
        __syncthreads();

        uint32_t aB[3] = {sb + OXH, sb + OXL, sb + OXH};
        uint32_t bB[3] = {sb + OWH, sb + OWH, sb + OWL};
#pragma unroll
        for (int p = 0; p < 3; p++) {
#pragma unroll
            for (int k0 = 0; k0 < 64; k0 += 16) {
                uint32_t af[4][4], bf_[2][2];
#pragma unroll
                for (int mf = 0; mf < 4; mf++)
                    ldmx4(af[mf], aB[p] + ((wm + mf * 16 + arow) * QST + k0 + ahalf * 8) * 2);
#pragma unroll
                for (int nf = 0; nf < 2; nf++)
                    ldmx2(bf_[nf], bB[p] + ((wn + nf * 8 + brow) * QST + k0 + bhalf * 8) * 2);
#pragma unroll
                for (int mf = 0; mf < 4; mf++)
#pragma unroll
                    for (int nf = 0; nf < 2; nf++) mma16816(acc[mf][nf], af[mf], bf_[nf]);
            }
        }
    }

    int gr = lane >> 2, tg2 = (lane & 3) * 2;
    if (MODE == 0) {
#pragma unroll
        for (int mf = 0; mf < 4; mf++)
#pragma unroll
            for (int hf = 0; hf < 2; hf++)
#pragma unroll
                for (int nf = 0; nf < 2; nf++) {
                    int a = m0 + wm + mf * 16 + hf * 8 + gr;
                    int col = n0 + wn + nf * 8 + tg2;
                    float d0 = acc[mf][nf][hf * 2], d1 = acc[mf][nf][hf * 2 + 1];
                    uint32_t hv = pack2bf(d0, d1);
                    __nv_bfloat162 hb = *(__nv_bfloat162*)&hv;
                    uint32_t lv = pack2bf(d0 - __bfloat162float(hb.x), d1 - __bfloat162float(hb.y));
                    *(uint32_t*)(Oh + (size_t)a * 256 + col) = hv;
                    *(uint32_t*)(Ol + (size_t)a * 256 + col) = lv;
                }
    } else {
        // transpose through smem: TS[colLocal][row], stride VST
        __syncthreads();
        __nv_bfloat16* TSh = (__nv_bfloat16*)sm;
        __nv_bfloat16* TSl = TSh + 64 * VST;
#pragma unroll
        for (int mf = 0; mf < 4; mf++)
#pragma unroll
            for (int hf = 0; hf < 2; hf++)
#pragma unroll
                for (int nf = 0; nf < 2; nf++) {
                    int row = wm + mf * 16 + hf * 8 + gr;
                    int cl = wn + nf * 8 + tg2;
                    float d0 = acc[mf][nf][hf * 2], d1 = acc[mf][nf][hf * 2 + 1];
                    __nv_bfloat16 h0 = __float2bfloat16_rn(d0);
                    __nv_bfloat16 h1 = __float2bfloat16_rn(d1);
                    TSh[cl * VST + row] = h0;
                    TSh[(cl + 1) * VST + row] = h1;
                    TSl[cl * VST + row] = __float2bfloat16_rn(d0 - __bfloat162float(h0));
                    TSl[(cl + 1) * VST + row] = __float2bfloat16_rn(d1 - __bfloat162float(h1));
                }
        __syncthreads();
        int jl = tid >> 2, ch = tid & 3;   // 64 rows x 4 chunks of 32
#pragma unroll
        for (int u = 0; u < 4; u++) {
            *(uint4*)(Oh + (size_t)(n0 + jl) * NB + m0 + ch * 32 + u * 8) =
                *(const uint4*)(TSh + jl * VST + ch * 32 + u * 8);
            *(uint4*)(Ol + (size_t)(n0 + jl) * NB + m0 + ch * 32 + u * 8) =
                *(const uint4*)(TSl + jl * VST + ch * 32 + u * 8);
        }
    }
}

// ---------------- fused flash attention ----------------
// CTA: 128 a-rows x 1 head. grid (32, 4). Streams 32 b-tiles of 128.
// smem offsets (bytes):
#define OQH 0
#define OQL 18432
#define OK0 36864            // stage s: Kh at OK0 + s*36864, Kl at +18432
#define OVH 110592
#define OVL 128000
#define OPH 145408
#define OPL 180224
#define OSRED 215040
#define FUSED_SMEM 217088

__global__ __launch_bounds__(256, 1)
void attn_fused(const int* __restrict__ mask, const float* __restrict__ weight) {
    extern __shared__ char sm[];
    uint32_t sb = smem_u32(sm);
    int tid = threadIdx.x, wid = tid >> 5, lane = tid & 31;
    int at = blockIdx.x, h = blockIdx.y;
    int a0 = at * 128;
    int gr = lane >> 2, tg2 = (lane & 3) * 2;
    int arow = lane & 15, ahalf = lane >> 4;
    int brow = lane & 7, bhalf = (lane >> 3) & 1;
    int swm = (wid >> 2) * 64, swn = (wid & 3) * 32;   // S-phase warp tile
    int pwm = (wid >> 1) * 32, pwn = (wid & 1) * 32;   // PV-phase warp tile

    // stage Q (persistent)
#pragma unroll
    for (int it = 0; it < 4; it++) {
        int idx = tid + it * 256;
        int r = idx >> 3, c = idx & 7;
        *(uint4*)(sm + OQH + (r * QST + c * 8) * 2) = *(const uint4*)(QhB + (size_t)(a0 + r) * 256 + h * 64 + c * 8);
        *(uint4*)(sm + OQL + (r * QST + c * 8) * 2) = *(const uint4*)(QlB + (size_t)(a0 + r) * 256 + h * 64 + c * 8);
    }

    auto stage_K = [&](int st, int bt) {
        uint32_t kh = sb + OK0 + st * 36864, kl = kh + 18432;
#pragma unroll
        for (int it = 0; it < 4; it++) {
            int idx = tid + it * 256;
            int r = idx >> 3, c = idx & 7;
            uint32_t off = (uint32_t)(r * QST + c * 8) * 2;
            size_t g = (size_t)(bt * 128 + r) * 256 + h * 64 + c * 8;
            cp16(kh + off, KhB + g);
            cp16(kl + off, KlB + g);
        }
    };
    auto stage_V = [&](int bt) {
#pragma unroll
        for (int it = 0; it < 4; it++) {
            int idx = tid + it * 256;          // 0..1023
            int r = idx >> 4, c = idx & 15;    // 64 rows x 16 chunks
            uint32_t off = (uint32_t)(r * VST + c * 8) * 2;
            size_t g = (size_t)(h * 64 + r) * NB + bt * 128 + c * 8;
            cp16(sb + OVH + off, VtH + g);
            cp16(sb + OVL + off, VtL + g);
        }
    };

    stage_K(0, 0);
    CP_COMMIT();

    float rsum[8];
#pragma unroll
    for (int i = 0; i < 8; i++) rsum[i] = 0.0f;
    float ctx[2][4][4];
#pragma unroll
    for (int i = 0; i < 2; i++)
#pragma unroll
        for (int j = 0; j < 4; j++)
#pragma unroll
            for (int t = 0; t < 4; t++) ctx[i][j][t] = 0.0f;

    for (int i = 0; i < 32; i++) {
        int st = i & 1;
        int b0 = i * 128;
        stage_V(i);
        CP_COMMIT();
        if (i < 31) {
            stage_K(st ^ 1, i + 1);
            CP_COMMIT();
            CP_WAIT2();            // K(i) ready
        } else {
            CP_WAIT1();
        }
        __syncthreads();

        // ---- S phase: 3-pass bf16 over k=64 ----
        float sacc[4][4][4];
#pragma unroll
        for (int a = 0; a < 4; a++)
#pragma unroll
            for (int b = 0; b < 4; b++)
#pragma unroll
                for (int t = 0; t < 4; t++) sacc[a][b][t] = 0.0f;

        uint32_t kh_a = sb + OK0 + st * 36864, kl_a = kh_a + 18432;
        uint32_t aB[3] = {sb + OQH, sb + OQL, sb + OQH};
        uint32_t bB[3] = {kh_a, kh_a, kl_a};
#pragma unroll
        for (int p = 0; p < 3; p++) {
#pragma unroll
            for (int k0 = 0; k0 < 64; k0 += 16) {
                uint32_t af[4][4], bf_[4][2];
#pragma unroll
                for (int mf = 0; mf < 4; mf++)
                    ldmx4(af[mf], aB[p] + ((swm + mf * 16 + arow) * QST + k0 + ahalf * 8) * 2);
#pragma unroll
                for (int nf = 0; nf < 4; nf++)
                    ldmx2(bf_[nf], bB[p] + ((swn + nf * 8 + brow) * QST + k0 + bhalf * 8) * 2);
#pragma unroll
                for (int mf = 0; mf < 4; mf++)
#pragma unroll
                    for (int nf = 0; nf < 4; nf++) mma16816(sacc[mf][nf], af[mf], bf_[nf]);
            }
        }

        // ---- epilogue: mask/weight/clip/exp -> P (smem bf16 hi/lo), rsum ----
#pragma unroll
        for (int mf = 0; mf < 4; mf++)
#pragma unroll
            for (int hf = 0; hf < 2; hf++) {
                int row = swm + mf * 16 + hf * 8 + gr;
                size_t base = (size_t)(a0 + row) * NB + b0 + swn;
                float rs = 0.0f;
#pragma unroll
                for (int nf = 0; nf < 4; nf++) {
                    int2 m = *(const int2*)(mask + base + nf * 8 + tg2);
                    float2 w = *(const float2*)(weight + base + nf * 8 + tg2);
                    float d0 = sacc[mf][nf][hf * 2], d1 = sacc[mf][nf][hf * 2 + 1];
                    float s0 = m.x ? d0 * 0.125f : -10000.0f;
                    float s1 = m.y ? d1 * 0.125f : -10000.0f;
                    s0 += sanitize_f(w.x);
                    s1 += sanitize_f(w.y);
                    s0 = fminf(fmaxf(s0, -10.0f), 10.0f);
                    s1 = fminf(fmaxf(s1, -10.0f), 10.0f);
                    float e0 = __expf(s0), e1 = __expf(s1);
                    rs += e0 + e1;
                    int col = swn + nf * 8 + tg2;
                    uint32_t hv = pack2bf(e0, e1);
                    __nv_bfloat162 hb = *(__nv_bfloat162*)&hv;
                    uint32_t lv = pack2bf(e0 - __bfloat162float(hb.x), e1 - __bfloat162float(hb.y));
                    *(uint32_t*)(sm + OPH + (row * VST + col) * 2) = hv;
                    *(uint32_t*)(sm + OPL + (row * VST + col) * 2) = lv;
                }
                rsum[mf * 2 + hf] += rs;
            }

        if (i < 31) CP_WAIT1(); else CP_WAIT0();   // V(i) ready
        __syncthreads();

        // ---- PV phase: ctx += P * Vt, 3-pass ----
        uint32_t aB2[3] = {sb + OPH, sb + OPL, sb + OPH};
        uint32_t bB2[3] = {sb + OVH, sb + OVH, sb + OVL};
#pragma unroll
        for (int p = 0; p < 3; p++) {
#pragma unroll
            for (int ks = 0; ks < 8; ks++) {
                uint32_t af[2][4], bf_[4][2];
#pragma unroll
                for (int mf = 0; mf < 2; mf++)
                    ldmx4(af[mf], aB2[p] + ((pwm + mf * 16 + arow) * VST + ks * 16 + ahalf * 8) * 2);
#pragma unroll
                for (int nf = 0; nf < 4; nf++)
                    ldmx2(bf_[nf], bB2[p] + ((pwn + nf * 8 + brow) * VST + ks * 16 + bhalf * 8) * 2);
#pragma unroll
                for (int mf = 0; mf < 2; mf++)
#pragma unroll
                    for (int nf = 0; nf < 4; nf++) mma16816(ctx[mf][nf], af[mf], bf_[nf]);
            }
        }
        __syncthreads();   // P & V free for next tile
    }

    // ---- row sums: reduce over lane quad, cross-warp via smem ----
#pragma unroll
    for (int r = 0; r < 8; r++) {
        rsum[r] += __shfl_xor_sync(0xffffffffu, rsum[r], 1);
        rsum[r] += __shfl_xor_sync(0xffffffffu, rsum[r], 2);
    }
    float* Sred = (float*)(sm + OSRED);
    if ((lane & 3) == 0) {
#pragma unroll
        for (int mf = 0; mf < 4; mf++)
#pragma unroll
            for (int hf = 0; hf < 2; hf++)
                Sred[(wid & 3) * 128 + swm + mf * 16 + hf * 8 + gr] = rsum[mf * 2 + hf];
    }
    __syncthreads();
    if (tid < 128) {
        float t = Sred[tid] + Sred[128 + tid] + Sred[256 + tid] + Sred[384 + tid];
        Sred[tid] = 0.25f / t;   // includes head-mean
    }
    __syncthreads();

    // ---- writeout: normalized ctx -> CtxHd[h] ----
#pragma unroll
    for (int mf = 0; mf < 2; mf++)
#pragma unroll
        for (int hf = 0; hf < 2; hf++) {
            int row = pwm + mf * 16 + hf * 8 + gr;
            float sc = Sred[row];
#pragma unroll
            for (int nf = 0; nf < 4; nf++) {
                float2 v;
                v.x = ctx[mf][nf][hf * 2] * sc;
                v.y = ctx[mf][nf][hf * 2 + 1] * sc;
                int col = pwn + nf * 8 + tg2;
                *(float2*)(&CtxHd[h][(size_t)(a0 + row) * 64 + col]) = v;
            }
        }
}

// ---------------- combine ----------------
__global__ void combine_kernel(float* __restrict__ out) {
    int idx = blockIdx.x * 256 + threadIdx.x;  // NA*DK
    int a = idx >> 6, j = idx & 63;
    out[idx] = CtxHd[0][idx] + CtxHd[1][idx] + CtxHd[2][idx] + CtxHd[3][idx];
    if (j == 0) out[NA * DK + a] = 1.0f;   // influence == 1 exactly
}

extern "C" void kernel_launch(void* const* d_in, const int* in_sizes, int n_in,
                              void* d_out, int out_size) {
    const float* a_z    = (const float*)d_in[0];
    const float* bv_z   = (const float*)d_in[1];
    const int*   mask   = (const int*)d_in[2];
    const float* weight = (const float*)d_in[3];
    const float* Wq     = (const float*)d_in[4];
    const float* Wk     = (const float*)d_in[5];
    const float* Wv     = (const float*)d_in[6];
    float* out = (float*)d_out;

    __nv_bfloat16 *ah, *al, *bh, *bl, *wh, *wl, *qh, *ql, *kh, *kl, *vth, *vtl;
    cudaGetSymbolAddress((void**)&ah, AhB);  cudaGetSymbolAddress((void**)&al, AlB);
    cudaGetSymbolAddress((void**)&bh, BhB);  cudaGetSymbolAddress((void**)&bl, BlB);
    cudaGetSymbolAddress((void**)&wh, WHb);  cudaGetSymbolAddress((void**)&wl, WLb);
    cudaGetSymbolAddress((void**)&qh, QhB);  cudaGetSymbolAddress((void**)&ql, QlB);
    cudaGetSymbolAddress((void**)&kh, KhB);  cudaGetSymbolAddress((void**)&kl, KlB);
    cudaGetSymbolAddress((void**)&vth, VtH); cudaGetSymbolAddress((void**)&vtl, VtL);

    split_kernel<<<NA * D / 256, 256>>>(a_z, ah, al, NA * D, 1);
    split_kernel<<<NB * D / 256, 256>>>(bv_z, bh, bl, NB * D, 1);
    split_kernel<<<D * D / 256, 256>>>(Wq, wh + 0 * D * D, wl + 0 * D * D, D * D, 0);
    split_kernel<<<D * D / 256, 256>>>(Wk, wh + 1 * D * D, wl + 1 * D * D, D * D, 0);
    split_kernel<<<D * D / 256, 256>>>(Wv, wh + 2 * D * D, wl + 2 * D * D, D * D, 0);

    int proj_smem = (2 * 128 * QST + 2 * 64 * QST) * 2;   // 55296
    cudaFuncSetAttribute(proj_mma<0>, cudaFuncAttributeMaxDynamicSharedMemorySize, proj_smem);
    cudaFuncSetAttribute(proj_mma<1>, cudaFuncAttributeMaxDynamicSharedMemorySize, proj_smem);
    dim3 pg(32, 4);
    proj_mma<0><<<pg, 256, proj_smem>>>(ah, al, wh + 0 * D * D, wl + 0 * D * D, qh, ql);
    proj_mma<0><<<pg, 256, proj_smem>>>(bh, bl, wh + 1 * D * D, wl + 1 * D * D, kh, kl);
    proj_mma<1><<<pg, 256, proj_smem>>>(bh, bl, wh + 2 * D * D, wl + 2 * D * D, vth, vtl);

    cudaFuncSetAttribute(attn_fused, cudaFuncAttributeMaxDynamicSharedMemorySize, FUSED_SMEM);
    attn_fused<<<dim3(32, 4), 256, FUSED_SMEM>>>(mask, weight);

    combine_kernel<<<NA * DK / 256, 256>>>(out);
}

// round 11
// speedup vs baseline: 10.1584x; 1.3922x over previous
#include <cuda_runtime.h>
#include <cuda_bf16.h>
#include <math.h>
#include <stdint.h>

#define NA 4096
#define NB 4096
#define D  256
#define H  4
#define DK 64
#define QST 72    // Q/K smem row stride (bf16)
#define VST 136   // Vt/P/W smem row stride (elems)

// ---------------- device-global scratch ----------------
__device__ __nv_bfloat16 AhB[NA * D], AlB[NA * D];
__device__ __nv_bfloat16 BhB[NB * D], BlB[NB * D];
__device__ __nv_bfloat16 WHb[3][D * D], WLb[3][D * D];
__device__ __nv_bfloat16 QhB[NA * D], QlB[NA * D];
__device__ __nv_bfloat16 KhB[NB * D], KlB[NB * D];
__device__ __nv_bfloat16 VtH[D * NB], VtL[D * NB];   // [h*64+j][b]
__device__ short Wprep[(size_t)NA * NB];             // 32MB: (sanitize(w) + mask offset) * 2048
__device__ float CtxHd[H][NA * DK];

__device__ __forceinline__ float sanitize_f(float x) {
    if (isnan(x)) return 0.0f;
    if (isinf(x)) return x > 0.0f ? 1.0f : -1.0f;
    return x;
}

// ---------------- generic PTX helpers (sm_80+ only) ----------------
__device__ __forceinline__ uint32_t smem_u32(const void* p) {
    uint32_t a;
    asm("{ .reg .u64 t; cvta.to.shared.u64 t, %1; cvt.u32.u64 %0, t; }" : "=r"(a) : "l"(p));
    return a;
}
__device__ __forceinline__ void ldmx4(uint32_t* r, uint32_t addr) {
    asm volatile("ldmatrix.sync.aligned.m8n8.x4.shared.b16 {%0,%1,%2,%3}, [%4];"
                 : "=r"(r[0]), "=r"(r[1]), "=r"(r[2]), "=r"(r[3]) : "r"(addr));
}
__device__ __forceinline__ void mma16816(float* c, const uint32_t* a, const uint32_t* b) {
    asm volatile(
        "mma.sync.aligned.m16n8k16.row.col.f32.bf16.bf16.f32 "
        "{%0,%1,%2,%3}, {%4,%5,%6,%7}, {%8,%9}, {%0,%1,%2,%3};"
        : "+f"(c[0]), "+f"(c[1]), "+f"(c[2]), "+f"(c[3])
        : "r"(a[0]), "r"(a[1]), "r"(a[2]), "r"(a[3]), "r"(b[0]), "r"(b[1]));
}
__device__ __forceinline__ void cp16(uint32_t dst, const void* src) {
    asm volatile("cp.async.cg.shared.global [%0], [%1], 16;" :: "r"(dst), "l"(src));
}
#define CP_COMMIT() asm volatile("cp.async.commit_group;" ::: "memory")
#define CP_WAIT0()  asm volatile("cp.async.wait_group 0;" ::: "memory")
#define CP_WAIT1()  asm volatile("cp.async.wait_group 1;" ::: "memory")

__device__ __forceinline__ uint32_t pack2bf(float a, float b) {
    __nv_bfloat162 t;
    t.x = __float2bfloat16_rn(a);
    t.y = __float2bfloat16_rn(b);
    return *(uint32_t*)&t;
}

// B-operand loader: one ldmatrix.x4 = fragments for two adjacent n-groups (nfp*2, nfp*2+1)
__device__ __forceinline__ void ldmxB4(uint32_t* r, uint32_t base, int stride, int wn,
                                       int nfp, int k0, int lane) {
    int row = wn + nfp * 16 + (lane >> 4) * 8 + (lane & 7);
    int kh = ((lane >> 3) & 1) * 8;
    ldmx4(r, base + (uint32_t)(row * stride + k0 + kh) * 2);
}

// ---------------- split fp32 -> bf16 hi/lo ----------------
__global__ void split_kernel(const float* __restrict__ src, __nv_bfloat16* __restrict__ hi,
                             __nv_bfloat16* __restrict__ lo, int n, int dosan, float scale) {
    int i = blockIdx.x * 256 + threadIdx.x;
    if (i >= n) return;
    float x = src[i];
    if (dosan) x = sanitize_f(x);
    x *= scale;
    __nv_bfloat16 xh = __float2bfloat16_rn(x);
    hi[i] = xh;
    lo[i] = __float2bfloat16_rn(x - __bfloat162float(xh));
}

// ---------------- W' = (sanitize(w) + (m?0:-10000)) quantized x2048 int16 ----------------
__global__ void prep_w(const int* __restrict__ mask, const float* __restrict__ weight) {
    size_t i = ((size_t)blockIdx.x * 256 + threadIdx.x) * 8;
    short r[8];
#pragma unroll
    for (int u = 0; u < 2; u++) {
        int4 m = *(const int4*)(mask + i + u * 4);
        float4 w = *(const float4*)(weight + i + u * 4);
        int mi[4] = {m.x, m.y, m.z, m.w};
        float wi[4] = {w.x, w.y, w.z, w.w};
#pragma unroll
        for (int t = 0; t < 4; t++) {
            float ws = fminf(fmaxf(sanitize_f(wi[t]), -15.9f), 15.9f);
            r[u * 4 + t] = mi[t] ? (short)__float2int_rn(ws * 2048.0f) : (short)-32768;
        }
    }
    *(uint4*)(Wprep + i) = *(uint4*)r;
}

// ---------------- projection via mma.sync, 3-pass bf16 ----------------
// OUT[4096,256] = X @ W^T. MODE 0: [n][256] hi/lo. MODE 1: transposed Vt[j][n] hi/lo.
template <int MODE>
__global__ __launch_bounds__(256)
void proj_mma(const __nv_bfloat16* __restrict__ Xh, const __nv_bfloat16* __restrict__ Xl,
              const __nv_bfloat16* __restrict__ Wh, const __nv_bfloat16* __restrict__ Wl,
              __nv_bfloat16* __restrict__ Oh, __nv_bfloat16* __restrict__ Ol) {
    extern __shared__ char sm[];
    const int OXH = 0, OXL = 128 * QST * 2, OWH = 2 * 128 * QST * 2, OWL = OWH + 64 * QST * 2;
    uint32_t sb = smem_u32(sm);
    int tid = threadIdx.x, wid = tid >> 5, lane = tid & 31;
    int m0 = blockIdx.x * 128, n0 = blockIdx.y * 64;
    int wm = (wid >> 2) * 64, wn = (wid & 3) * 16;
    int arow = lane & 15, ahalf = lane >> 4;

    float acc[4][2][4];
#pragma unroll
    for (int i = 0; i < 4; i++)
#pragma unroll
        for (int j = 0; j < 2; j++)
#pragma unroll
            for (int t = 0; t < 4; t++) acc[i][j][t] = 0.0f;

    for (int kc = 0; kc < 4; kc++) {
        int k0g = kc * 64;
        __syncthreads();
#pragma unroll
        for (int it = 0; it < 4; it++) {
            int idx = tid + it * 256;
            int r = idx >> 3, c = idx & 7;
            *(uint4*)(sm + OXH + (r * QST + c * 8) * 2) = *(const uint4*)(Xh + (size_t)(m0 + r) * 256 + k0g + c * 8);
            *(uint4*)(sm + OXL + (r * QST + c * 8) * 2) = *(const uint4*)(Xl + (size_t)(m0 + r) * 256 + k0g + c * 8);
        }
#pragma unroll
        for (int it = 0; it < 2; it++) {
            int idx = tid + it * 256;
            int r = idx >> 3, c = idx & 7;
            *(uint4*)(sm + OWH + (r * QST + c * 8) * 2) = *(const uint4*)(Wh + (size_t)(n0 + r) * 256 + k0g + c * 8);
            *(uint4*)(sm + OWL + (r * QST + c * 8) * 2) = *(const uint4*)(Wl + (size_t)(n0 + r) * 256 + k0g + c * 8);
        }
        __syncthreads();

        uint32_t aB[3] = {sb + OXH, sb + OXL, sb + OXH};
        uint32_t bB[3] = {sb + OWH, sb + OWH, sb + OWL};
#pragma unroll
        for (int p = 0; p < 3; p++) {
#pragma unroll
            for (int k0 = 0; k0 < 64; k0 += 16) {
                uint32_t af[4][4], bf_[4];
#pragma unroll
                for (int mf = 0; mf < 4; mf++)
                    ldmx4(af[mf], aB[p] + ((wm + mf * 16 + arow) * QST + k0 + ahalf * 8) * 2);
                ldmxB4(bf_, bB[p], QST, wn, 0, k0, lane);
#pragma unroll
                for (int mf = 0; mf < 4; mf++) {
                    mma16816(acc[mf][0], af[mf], bf_);
                    mma16816(acc[mf][1], af[mf], bf_ + 2);
                }
            }
        }
    }

    int gr = lane >> 2, tg2 = (lane & 3) * 2;
    if (MODE == 0) {
#pragma unroll
        for (int mf = 0; mf < 4; mf++)
#pragma unroll
            for (int hf = 0; hf < 2; hf++)
#pragma unroll
                for (int nf = 0; nf < 2; nf++) {
                    int a = m0 + wm + mf * 16 + hf * 8 + gr;
                    int col = n0 + wn + nf * 8 + tg2;
                    float d0 = acc[mf][nf][hf * 2], d1 = acc[mf][nf][hf * 2 + 1];
                    uint32_t hv = pack2bf(d0, d1);
                    __nv_bfloat162 hb = *(__nv_bfloat162*)&hv;
                    uint32_t lv = pack2bf(d0 - __bfloat162float(hb.x), d1 - __bfloat162float(hb.y));
                    *(uint32_t*)(Oh + (size_t)a * 256 + col) = hv;
                    *(uint32_t*)(Ol + (size_t)a * 256 + col) = lv;
                }
    } else {
        __syncthreads();
        __nv_bfloat16* TSh = (__nv_bfloat16*)sm;
        __nv_bfloat16* TSl = TSh + 64 * VST;
#pragma unroll
        for (int mf = 0; mf < 4; mf++)
#pragma unroll
            for (int hf = 0; hf < 2; hf++)
#pragma unroll
                for (int nf = 0; nf < 2; nf++) {
                    int row = wm + mf * 16 + hf * 8 + gr;
                    int cl = wn + nf * 8 + tg2;
                    float d0 = acc[mf][nf][hf * 2], d1 = acc[mf][nf][hf * 2 + 1];
                    __nv_bfloat16 h0 = __float2bfloat16_rn(d0);
                    __nv_bfloat16 h1 = __float2bfloat16_rn(d1);
                    TSh[cl * VST + row] = h0;
                    TSh[(cl + 1) * VST + row] = h1;
                    TSl[cl * VST + row] = __float2bfloat16_rn(d0 - __bfloat162float(h0));
                    TSl[(cl + 1) * VST + row] = __float2bfloat16_rn(d1 - __bfloat162float(h1));
                }
        __syncthreads();
        int jl = tid >> 2, ch = tid & 3;
#pragma unroll
        for (int u = 0; u < 4; u++) {
            *(uint4*)(Oh + (size_t)(n0 + jl) * NB + m0 + ch * 32 + u * 8) =
                *(const uint4*)(TSh + jl * VST + ch * 32 + u * 8);
            *(uint4*)(Ol + (size_t)(n0 + jl) * NB + m0 + ch * 32 + u * 8) =
                *(const uint4*)(TSl + jl * VST + ch * 32 + u * 8);
        }
    }
}

// ---------------- fused flash attention ----------------
// CTA: 128 a-rows x 1 head. grid (32, 4). 32 b-tiles of 128.
// 3-pass S (QhKh + QlKh + QhKl), 3-pass PV (PhVh + PlVh + PhVl).
// W' (int16) prefetched via cp.async; no mask/weight gmem loads in epilogue.
#define OQH 0
#define OQL 18432
#define OKH 36864
#define OKL 55296
#define OVH 73728
#define OVL 91136
#define OPH 108544
#define OPL 143360
#define OW  178176
#define OSRED 212992
#define FUSED_SMEM 215040

__global__ __launch_bounds__(256, 1)
void attn_fused() {
    extern __shared__ char sm[];
    uint32_t sb = smem_u32(sm);
    int tid = threadIdx.x, wid = tid >> 5, lane = tid & 31;
    int at = blockIdx.x, h = blockIdx.y;
    int a0 = at * 128;
    int gr = lane >> 2, tg2 = (lane & 3) * 2;
    int arow = lane & 15, ahalf = lane >> 4;
    int swm = (wid >> 2) * 64, swn = (wid & 3) * 32;   // S-phase warp tile 64x32
    int pwm = (wid >> 1) * 32, pwn = (wid & 1) * 32;   // PV-phase warp tile 32x32

    // stage Q hi/lo (persistent)
#pragma unroll
    for (int it = 0; it < 4; it++) {
        int idx = tid + it * 256;
        int r = idx >> 3, c = idx & 7;
        *(uint4*)(sm + OQH + (r * QST + c * 8) * 2) = *(const uint4*)(QhB + (size_t)(a0 + r) * 256 + h * 64 + c * 8);
        *(uint4*)(sm + OQL + (r * QST + c * 8) * 2) = *(const uint4*)(QlB + (size_t)(a0 + r) * 256 + h * 64 + c * 8);
    }

    auto stage_K = [&](int bt) {
#pragma unroll
        for (int it = 0; it < 4; it++) {
            int idx = tid + it * 256;
            int r = idx >> 3, c = idx & 7;
            uint32_t off = (uint32_t)(r * QST + c * 8) * 2;
            size_t g = (size_t)(bt * 128 + r) * 256 + h * 64 + c * 8;
            cp16(sb + OKH + off, KhB + g);
            cp16(sb + OKL + off, KlB + g);
        }
    };
    auto stage_V = [&](int bt) {
#pragma unroll
        for (int it = 0; it < 4; it++) {
            int idx = tid + it * 256;          // 0..1023: 64 rows x 16 chunks
            int r = idx >> 4, c = idx & 15;
            uint32_t off = (uint32_t)(r * VST + c * 8) * 2;
            size_t g = (size_t)(h * 64 + r) * NB + bt * 128 + c * 8;
            cp16(sb + OVH + off, VtH + g);
            cp16(sb + OVL + off, VtL + g);
        }
    };
    auto stage_W = [&](int bt) {
#pragma unroll
        for (int it = 0; it < 8; it++) {
            int idx = tid + it * 256;          // 0..2047: 128 rows x 16 chunks
            int r = idx >> 4, c = idx & 15;
            cp16(sb + OW + (uint32_t)(r * VST + c * 8) * 2,
                 Wprep + (size_t)(a0 + r) * NB + bt * 128 + c * 8);
        }
    };

    stage_K(0);
    CP_COMMIT();

    float rsum[8];
#pragma unroll
    for (int i = 0; i < 8; i++) rsum[i] = 0.0f;
    float ctx[2][4][4];
#pragma unroll
    for (int i = 0; i < 2; i++)
#pragma unroll
        for (int j = 0; j < 4; j++)
#pragma unroll
            for (int t = 0; t < 4; t++) ctx[i][j][t] = 0.0f;

    for (int i = 0; i < 32; i++) {
        stage_V(i);
        stage_W(i);
        CP_COMMIT();      // group A_i
        CP_WAIT1();       // K(i) done (older group)
        __syncthreads();

        // ---- S phase: 3-pass ----
        float sacc[4][4][4];
#pragma unroll
        for (int a = 0; a < 4; a++)
#pragma unroll
            for (int b = 0; b < 4; b++)
#pragma unroll
                for (int t = 0; t < 4; t++) sacc[a][b][t] = 0.0f;

        uint32_t aB[3] = {sb + OQH, sb + OQL, sb + OQH};
        uint32_t bB[3] = {sb + OKH, sb + OKH, sb + OKL};
#pragma unroll
        for (int p = 0; p < 3; p++) {
#pragma unroll
            for (int k0 = 0; k0 < 64; k0 += 16) {
                uint32_t af[4][4], bf0[4], bf1[4];
#pragma unroll
                for (int mf = 0; mf < 4; mf++)
                    ldmx4(af[mf], aB[p] + ((swm + mf * 16 + arow) * QST + k0 + ahalf * 8) * 2);
                ldmxB4(bf0, bB[p], QST, swn, 0, k0, lane);
                ldmxB4(bf1, bB[p], QST, swn, 1, k0, lane);
#pragma unroll
                for (int mf = 0; mf < 4; mf++) {
                    mma16816(sacc[mf][0], af[mf], bf0);
                    mma16816(sacc[mf][1], af[mf], bf0 + 2);
                    mma16816(sacc[mf][2], af[mf], bf1);
                    mma16816(sacc[mf][3], af[mf], bf1 + 2);
                }
            }
        }

        CP_WAIT0();   // V(i), W'(i) ready

        // ---- epilogue: s = clip(d + w') -> exp -> P hi/lo (smem), rsum ----
#pragma unroll
        for (int mf = 0; mf < 4; mf++)
#pragma unroll
            for (int hf = 0; hf < 2; hf++) {
                int row = swm + mf * 16 + hf * 8 + gr;
                float rs = 0.0f;
#pragma unroll
                for (int nf = 0; nf < 4; nf++) {
                    int col = swn + nf * 8 + tg2;
                    uint32_t wp = *(uint32_t*)(sm + OW + (row * VST + col) * 2);
                    short2 ws = *(short2*)&wp;
                    float s0 = sacc[mf][nf][hf * 2]     + (float)ws.x * (1.0f / 2048.0f);
                    float s1 = sacc[mf][nf][hf * 2 + 1] + (float)ws.y * (1.0f / 2048.0f);
                    s0 = fminf(fmaxf(s0, -10.0f), 10.0f);
                    s1 = fminf(fmaxf(s1, -10.0f), 10.0f);
                    float e0 = __expf(s0), e1 = __expf(s1);
                    rs += e0 + e1;
                    uint32_t hv = pack2bf(e0, e1);
                    __nv_bfloat162 hb = *(__nv_bfloat162*)&hv;
                    uint32_t lv = pack2bf(e0 - __bfloat162float(hb.x), e1 - __bfloat162float(hb.y));
                    *(uint32_t*)(sm + OPH + (row * VST + col) * 2) = hv;
                    *(uint32_t*)(sm + OPL + (row * VST + col) * 2) = lv;
                }
                rsum[mf * 2 + hf] += rs;
            }
        __syncthreads();   // P visible; all warps done with K

        if (i < 31) {
            stage_K(i + 1);
            CP_COMMIT();   // overlaps with PV phase
        }

        // ---- PV phase: ctx += P * Vt, 3-pass ----
        uint32_t aB2[3] = {sb + OPH, sb + OPL, sb + OPH};
        uint32_t bB2[3] = {sb + OVH, sb + OVH, sb + OVL};
#pragma unroll
        for (int p = 0; p < 3; p++) {
#pragma unroll
            for (int ks = 0; ks < 8; ks++) {
                uint32_t af[2][4], bf0[4], bf1[4];
#pragma unroll
                for (int mf = 0; mf < 2; mf++)
                    ldmx4(af[mf], aB2[p] + ((pwm + mf * 16 + arow) * VST + ks * 16 + ahalf * 8) * 2);
                ldmxB4(bf0, bB2[p], VST, pwn, 0, ks * 16, lane);
                ldmxB4(bf1, bB2[p], VST, pwn, 1, ks * 16, lane);
#pragma unroll
                for (int mf = 0; mf < 2; mf++) {
                    mma16816(ctx[mf][0], af[mf], bf0);
                    mma16816(ctx[mf][1], af[mf], bf0 + 2);
                    mma16816(ctx[mf][2], af[mf], bf1);
                    mma16816(ctx[mf][3], af[mf], bf1 + 2);
                }
            }
        }
        __syncthreads();   // P & V & W' free for next tile
    }

    // ---- row sums: quad reduce + cross-warp via smem ----
#pragma unroll
    for (int r = 0; r < 8; r++) {
        rsum[r] += __shfl_xor_sync(0xffffffffu, rsum[r], 1);
        rsum[r] += __shfl_xor_sync(0xffffffffu, rsum[r], 2);
    }
    float* Sred = (float*)(sm + OSRED);
    if ((lane & 3) == 0) {
#pragma unroll
        for (int mf = 0; mf < 4; mf++)
#pragma unroll
            for (int hf = 0; hf < 2; hf++)
                Sred[(wid & 3) * 128 + swm + mf * 16 + hf * 8 + gr] = rsum[mf * 2 + hf];
    }
    __syncthreads();
    if (tid < 128) {
        float t = Sred[tid] + Sred[128 + tid] + Sred[256 + tid] + Sred[384 + tid];
        Sred[tid] = 0.25f / t;   // includes head-mean
    }
    __syncthreads();

    // ---- writeout ----
#pragma unroll
    for (int mf = 0; mf < 2; mf++)
#pragma unroll
        for (int hf = 0; hf < 2; hf++) {
            int row = pwm + mf * 16 + hf * 8 + gr;
            float sc = Sred[row];
#pragma unroll
            for (int nf = 0; nf < 4; nf++) {
                float2 v;
                v.x = ctx[mf][nf][hf * 2] * sc;
                v.y = ctx[mf][nf][hf * 2 + 1] * sc;
                *(float2*)(&CtxHd[h][(size_t)(a0 + row) * 64 + pwn + nf * 8 + tg2]) = v;
            }
        }
}

// ---------------- combine ----------------
__global__ void combine_kernel(float* __restrict__ out) {
    int idx = blockIdx.x * 256 + threadIdx.x;
    int a = idx >> 6, j = idx & 63;
    out[idx] = CtxHd[0][idx] + CtxHd[1][idx] + CtxHd[2][idx] + CtxHd[3][idx];
    if (j == 0) out[NA * DK + a] = 1.0f;   // influence == 1 exactly
}

extern "C" void kernel_launch(void* const* d_in, const int* in_sizes, int n_in,
                              void* d_out, int out_size) {
    const float* a_z    = (const float*)d_in[0];
    const float* bv_z   = (const float*)d_in[1];
    const int*   mask   = (const int*)d_in[2];
    const float* weight = (const float*)d_in[3];
    const float* Wq     = (const float*)d_in[4];
    const float* Wk     = (const float*)d_in[5];
    const float* Wv     = (const float*)d_in[6];
    float* out = (float*)d_out;

    __nv_bfloat16 *ah, *al, *bh, *bl, *wh, *wl, *qh, *ql, *kh, *kl, *vth, *vtl;
    cudaGetSymbolAddress((void**)&ah, AhB);  cudaGetSymbolAddress((void**)&al, AlB);
    cudaGetSymbolAddress((void**)&bh, BhB);  cudaGetSymbolAddress((void**)&bl, BlB);
    cudaGetSymbolAddress((void**)&wh, WHb);  cudaGetSymbolAddress((void**)&wl, WLb);
    cudaGetSymbolAddress((void**)&qh, QhB);  cudaGetSymbolAddress((void**)&ql, QlB);
    cudaGetSymbolAddress((void**)&kh, KhB);  cudaGetSymbolAddress((void**)&kl, KlB);
    cudaGetSymbolAddress((void**)&vth, VtH); cudaGetSymbolAddress((void**)&vtl, VtL);

    split_kernel<<<NA * D / 256, 256>>>(a_z, ah, al, NA * D, 1, 1.0f);
    split_kernel<<<NB * D / 256, 256>>>(bv_z, bh, bl, NB * D, 1, 1.0f);
    split_kernel<<<D * D / 256, 256>>>(Wq, wh + 0 * D * D, wl + 0 * D * D, D * D, 0, 0.125f);
    split_kernel<<<D * D / 256, 256>>>(Wk, wh + 1 * D * D, wl + 1 * D * D, D * D, 0, 1.0f);
    split_kernel<<<D * D / 256, 256>>>(Wv, wh + 2 * D * D, wl + 2 * D * D, D * D, 0, 1.0f);

    prep_w<<<NA * NB / (256 * 8), 256>>>(mask, weight);

    int proj_smem = (2 * 128 * QST + 2 * 64 * QST) * 2;   // 55296
    cudaFuncSetAttribute(proj_mma<0>, cudaFuncAttributeMaxDynamicSharedMemorySize, proj_smem);
    cudaFuncSetAttribute(proj_mma<1>, cudaFuncAttributeMaxDynamicSharedMemorySize, proj_smem);
    dim3 pg(32, 4);
    proj_mma<0><<<pg, 256, proj_smem>>>(ah, al, wh + 0 * D * D, wl + 0 * D * D, qh, ql);
    proj_mma<0><<<pg, 256, proj_smem>>>(bh, bl, wh + 1 * D * D, wl + 1 * D * D, kh, kl);
    proj_mma<1><<<pg, 256, proj_smem>>>(bh, bl, wh + 2 * D * D, wl + 2 * D * D, vth, vtl);

    cudaFuncSetAttribute(attn_fused, cudaFuncAttributeMaxDynamicSharedMemorySize, FUSED_SMEM);
    attn_fused<<<dim3(32, 4), 256, FUSED_SMEM>>>();

    combine_kernel<<<NA * DK / 256, 256>>>(out);
}

// round 12
// speedup vs baseline: 14.0355x; 1.3817x over previous
#include <cuda_runtime.h>
#include <cuda_bf16.h>
#include <cuda_fp16.h>
#include <math.h>
#include <stdint.h>

#define NA 4096
#define NB 4096
#define D  256
#define H  4
#define DK 64
#define QST 72    // Q/K smem row stride (b16 elems)
#define VST 136   // Vt/P/W smem row stride (elems)

// ---------------- device-global scratch ----------------
__device__ __nv_bfloat16 AhB[NA * D], AlB[NA * D];
__device__ __nv_bfloat16 BhB[NB * D], BlB[NB * D];
__device__ __nv_bfloat16 WHb[3][D * D], WLb[3][D * D];
__device__ __half QhB[NA * D];
__device__ __half KhB[NB * D];
__device__ __half VtH[D * NB];                 // [h*64+j][b]
__device__ short Wprep[(size_t)NA * NB];       // (sanitize(w) + mask offset) * 2048
__device__ float CtxHd[H][NA * DK];

__device__ __forceinline__ float sanitize_f(float x) {
    if (isnan(x)) return 0.0f;
    if (isinf(x)) return x > 0.0f ? 1.0f : -1.0f;
    return x;
}

// ---------------- generic PTX helpers (sm_80+ only) ----------------
__device__ __forceinline__ uint32_t smem_u32(const void* p) {
    uint32_t a;
    asm("{ .reg .u64 t; cvta.to.shared.u64 t, %1; cvt.u32.u64 %0, t; }" : "=r"(a) : "l"(p));
    return a;
}
__device__ __forceinline__ void ldmx4(uint32_t* r, uint32_t addr) {
    asm volatile("ldmatrix.sync.aligned.m8n8.x4.shared.b16 {%0,%1,%2,%3}, [%4];"
                 : "=r"(r[0]), "=r"(r[1]), "=r"(r[2]), "=r"(r[3]) : "r"(addr));
}
__device__ __forceinline__ void mma_bf(float* c, const uint32_t* a, const uint32_t* b) {
    asm volatile(
        "mma.sync.aligned.m16n8k16.row.col.f32.bf16.bf16.f32 "
        "{%0,%1,%2,%3}, {%4,%5,%6,%7}, {%8,%9}, {%0,%1,%2,%3};"
        : "+f"(c[0]), "+f"(c[1]), "+f"(c[2]), "+f"(c[3])
        : "r"(a[0]), "r"(a[1]), "r"(a[2]), "r"(a[3]), "r"(b[0]), "r"(b[1]));
}
__device__ __forceinline__ void mma_fp(float* c, const uint32_t* a, const uint32_t* b) {
    asm volatile(
        "mma.sync.aligned.m16n8k16.row.col.f32.f16.f16.f32 "
        "{%0,%1,%2,%3}, {%4,%5,%6,%7}, {%8,%9}, {%0,%1,%2,%3};"
        : "+f"(c[0]), "+f"(c[1]), "+f"(c[2]), "+f"(c[3])
        : "r"(a[0]), "r"(a[1]), "r"(a[2]), "r"(a[3]), "r"(b[0]), "r"(b[1]));
}
__device__ __forceinline__ void cp16(uint32_t dst, const void* src) {
    asm volatile("cp.async.cg.shared.global [%0], [%1], 16;" :: "r"(dst), "l"(src));
}
#define CP_COMMIT() asm volatile("cp.async.commit_group;" ::: "memory")
#define CP_WAIT0()  asm volatile("cp.async.wait_group 0;" ::: "memory")

// B-operand loader: one ldmatrix.x4 = fragments for two adjacent n-groups
__device__ __forceinline__ void ldmxB4(uint32_t* r, uint32_t base, int stride, int wn,
                                       int nfp, int k0, int lane) {
    int row = wn + nfp * 16 + (lane >> 4) * 8 + (lane & 7);
    int kh = ((lane >> 3) & 1) * 8;
    ldmx4(r, base + (uint32_t)(row * stride + k0 + kh) * 2);
}

// ---------------- split fp32 -> bf16 hi/lo (proj inputs) ----------------
__global__ void split_kernel(const float* __restrict__ src, __nv_bfloat16* __restrict__ hi,
                             __nv_bfloat16* __restrict__ lo, int n, int dosan, float scale) {
    int i = blockIdx.x * 256 + threadIdx.x;
    if (i >= n) return;
    float x = src[i];
    if (dosan) x = sanitize_f(x);
    x *= scale;
    __nv_bfloat16 xh = __float2bfloat16_rn(x);
    hi[i] = xh;
    lo[i] = __float2bfloat16_rn(x - __bfloat162float(xh));
}

// ---------------- W' = (sanitize(w) + (m?0:-10000)) quantized x2048 int16 ----------------
__global__ void prep_w(const int* __restrict__ mask, const float* __restrict__ weight) {
    size_t i = ((size_t)blockIdx.x * 256 + threadIdx.x) * 8;
    short r[8];
#pragma unroll
    for (int u = 0; u < 2; u++) {
        int4 m = *(const int4*)(mask + i + u * 4);
        float4 w = *(const float4*)(weight + i + u * 4);
        int mi[4] = {m.x, m.y, m.z, m.w};
        float wi[4] = {w.x, w.y, w.z, w.w};
#pragma unroll
        for (int t = 0; t < 4; t++) {
            float ws = fminf(fmaxf(sanitize_f(wi[t]), -15.9f), 15.9f);
            r[u * 4 + t] = mi[t] ? (short)__float2int_rn(ws * 2048.0f) : (short)-32768;
        }
    }
    *(uint4*)(Wprep + i) = *(uint4*)r;
}

// ---------------- projection via mma.sync, 3-pass bf16 internal, fp16 output ----------------
// OUT[4096,256] = X @ W^T. MODE 0: [n][256] fp16. MODE 1: transposed Vt[j][n] fp16.
template <int MODE>
__global__ __launch_bounds__(256)
void proj_mma(const __nv_bfloat16* __restrict__ Xh, const __nv_bfloat16* __restrict__ Xl,
              const __nv_bfloat16* __restrict__ Wh, const __nv_bfloat16* __restrict__ Wl,
              __half* __restrict__ Oh) {
    extern __shared__ char sm[];
    const int OXH = 0, OXL = 128 * QST * 2, OWH = 2 * 128 * QST * 2, OWL = OWH + 64 * QST * 2;
    uint32_t sb = smem_u32(sm);
    int tid = threadIdx.x, wid = tid >> 5, lane = tid & 31;
    int m0 = blockIdx.x * 128, n0 = blockIdx.y * 64;
    int wm = (wid >> 2) * 64, wn = (wid & 3) * 16;
    int arow = lane & 15, ahalf = lane >> 4;

    float acc[4][2][4];
#pragma unroll
    for (int i = 0; i < 4; i++)
#pragma unroll
        for (int j = 0; j < 2; j++)
#pragma unroll
            for (int t = 0; t < 4; t++) acc[i][j][t] = 0.0f;

    for (int kc = 0; kc < 4; kc++) {
        int k0g = kc * 64;
        __syncthreads();
#pragma unroll
        for (int it = 0; it < 4; it++) {
            int idx = tid + it * 256;
            int r = idx >> 3, c = idx & 7;
            *(uint4*)(sm + OXH + (r * QST + c * 8) * 2) = *(const uint4*)(Xh + (size_t)(m0 + r) * 256 + k0g + c * 8);
            *(uint4*)(sm + OXL + (r * QST + c * 8) * 2) = *(const uint4*)(Xl + (size_t)(m0 + r) * 256 + k0g + c * 8);
        }
#pragma unroll
        for (int it = 0; it < 2; it++) {
            int idx = tid + it * 256;
            int r = idx >> 3, c = idx & 7;
            *(uint4*)(sm + OWH + (r * QST + c * 8) * 2) = *(const uint4*)(Wh + (size_t)(n0 + r) * 256 + k0g + c * 8);
            *(uint4*)(sm + OWL + (r * QST + c * 8) * 2) = *(const uint4*)(Wl + (size_t)(n0 + r) * 256 + k0g + c * 8);
        }
        __syncthreads();

        uint32_t aB[3] = {sb + OXH, sb + OXL, sb + OXH};
        uint32_t bB[3] = {sb + OWH, sb + OWH, sb + OWL};
#pragma unroll
        for (int p = 0; p < 3; p++) {
#pragma unroll
            for (int k0 = 0; k0 < 64; k0 += 16) {
                uint32_t af[4][4], bf_[4];
#pragma unroll
                for (int mf = 0; mf < 4; mf++)
                    ldmx4(af[mf], aB[p] + ((wm + mf * 16 + arow) * QST + k0 + ahalf * 8) * 2);
                ldmxB4(bf_, bB[p], QST, wn, 0, k0, lane);
#pragma unroll
                for (int mf = 0; mf < 4; mf++) {
                    mma_bf(acc[mf][0], af[mf], bf_);
                    mma_bf(acc[mf][1], af[mf], bf_ + 2);
                }
            }
        }
    }

    int gr = lane >> 2, tg2 = (lane & 3) * 2;
    if (MODE == 0) {
#pragma unroll
        for (int mf = 0; mf < 4; mf++)
#pragma unroll
            for (int hf = 0; hf < 2; hf++)
#pragma unroll
                for (int nf = 0; nf < 2; nf++) {
                    int a = m0 + wm + mf * 16 + hf * 8 + gr;
                    int col = n0 + wn + nf * 8 + tg2;
                    __half2 hv = __floats2half2_rn(acc[mf][nf][hf * 2], acc[mf][nf][hf * 2 + 1]);
                    *(__half2*)(Oh + (size_t)a * 256 + col) = hv;
                }
    } else {
        __syncthreads();
        __half* TSh = (__half*)sm;
#pragma unroll
        for (int mf = 0; mf < 4; mf++)
#pragma unroll
            for (int hf = 0; hf < 2; hf++)
#pragma unroll
                for (int nf = 0; nf < 2; nf++) {
                    int row = wm + mf * 16 + hf * 8 + gr;
                    int cl = wn + nf * 8 + tg2;
                    TSh[cl * VST + row] = __float2half_rn(acc[mf][nf][hf * 2]);
                    TSh[(cl + 1) * VST + row] = __float2half_rn(acc[mf][nf][hf * 2 + 1]);
                }
        __syncthreads();
        int jl = tid >> 2, ch = tid & 3;
#pragma unroll
        for (int u = 0; u < 4; u++)
            *(uint4*)(Oh + (size_t)(n0 + jl) * NB + m0 + ch * 32 + u * 8) =
                *(const uint4*)(TSh + jl * VST + ch * 32 + u * 8);
    }
}

// ---------------- fused flash attention (fp16, 1-pass S, 1-pass PV) ----------------
// CTA: 128 a-rows x 1 head. grid (32, 4). 32 b-tiles of 128, K/V/W' double-buffered.
#define OQ 0                                 // 128*72*2  = 18432
#define STG 18432                            // stage base
#define STG_SZ 70656                         // K 18432 + V 17408 + W 34816
#define SOK 0
#define SOV 18432
#define SOW 35840
#define OP  (STG + 2 * STG_SZ)               // 159744, P: 128*136*2 = 34816
#define OSRED (OP + 34816)                   // 194560
#define FUSED_SMEM (OSRED + 2048)            // 196608

__global__ __launch_bounds__(256, 1)
void attn_fused() {
    extern __shared__ char sm[];
    uint32_t sb = smem_u32(sm);
    int tid = threadIdx.x, wid = tid >> 5, lane = tid & 31;
    int at = blockIdx.x, h = blockIdx.y;
    int a0 = at * 128;
    int gr = lane >> 2, tg2 = (lane & 3) * 2;
    int arow = lane & 15, ahalf = lane >> 4;
    int swm = (wid >> 2) * 64, swn = (wid & 3) * 32;   // S warp tile 64x32
    int pwm = (wid >> 1) * 32, pwn = (wid & 1) * 32;   // PV warp tile 32x32

    // stage Q (persistent, fp16)
#pragma unroll
    for (int it = 0; it < 4; it++) {
        int idx = tid + it * 256;
        int r = idx >> 3, c = idx & 7;
        *(uint4*)(sm + OQ + (r * QST + c * 8) * 2) = *(const uint4*)(QhB + (size_t)(a0 + r) * 256 + h * 64 + c * 8);
    }

    auto stage_load = [&](int st, int bt) {
        uint32_t base = sb + STG + st * STG_SZ;
#pragma unroll
        for (int it = 0; it < 4; it++) {
            int idx = tid + it * 256;
            int r = idx >> 3, c = idx & 7;
            cp16(base + SOK + (uint32_t)(r * QST + c * 8) * 2,
                 KhB + (size_t)(bt * 128 + r) * 256 + h * 64 + c * 8);
        }
#pragma unroll
        for (int it = 0; it < 4; it++) {
            int idx = tid + it * 256;          // 64 rows x 16 chunks
            int r = idx >> 4, c = idx & 15;
            cp16(base + SOV + (uint32_t)(r * VST + c * 8) * 2,
                 VtH + (size_t)(h * 64 + r) * NB + bt * 128 + c * 8);
        }
#pragma unroll
        for (int it = 0; it < 8; it++) {
            int idx = tid + it * 256;          // 128 rows x 16 chunks
            int r = idx >> 4, c = idx & 15;
            cp16(base + SOW + (uint32_t)(r * VST + c * 8) * 2,
                 Wprep + (size_t)(a0 + r) * NB + bt * 128 + c * 8);
        }
    };

    stage_load(0, 0);
    CP_COMMIT();

    float rsum[8];
#pragma unroll
    for (int i = 0; i < 8; i++) rsum[i] = 0.0f;
    float ctx[2][4][4];
#pragma unroll
    for (int i = 0; i < 2; i++)
#pragma unroll
        for (int j = 0; j < 4; j++)
#pragma unroll
            for (int t = 0; t < 4; t++) ctx[i][j][t] = 0.0f;

    for (int i = 0; i < 32; i++) {
        int st = i & 1;
        uint32_t base = sb + STG + st * STG_SZ;
        CP_WAIT0();          // stage(i) resident
        __syncthreads();
        if (i < 31) {
            stage_load(st ^ 1, i + 1);   // prefetch under compute
            CP_COMMIT();
        }

        // ---- S phase: 1-pass fp16 ----
        float sacc[4][4][4];
#pragma unroll
        for (int a = 0; a < 4; a++)
#pragma unroll
            for (int b = 0; b < 4; b++)
#pragma unroll
                for (int t = 0; t < 4; t++) sacc[a][b][t] = 0.0f;

#pragma unroll
        for (int k0 = 0; k0 < 64; k0 += 16) {
            uint32_t af[4][4], bf0[4], bf1[4];
#pragma unroll
            for (int mf = 0; mf < 4; mf++)
                ldmx4(af[mf], sb + OQ + ((swm + mf * 16 + arow) * QST + k0 + ahalf * 8) * 2);
            ldmxB4(bf0, base + SOK, QST, swn, 0, k0, lane);
            ldmxB4(bf1, base + SOK, QST, swn, 1, k0, lane);
#pragma unroll
            for (int mf = 0; mf < 4; mf++) {
                mma_fp(sacc[mf][0], af[mf], bf0);
                mma_fp(sacc[mf][1], af[mf], bf0 + 2);
                mma_fp(sacc[mf][2], af[mf], bf1);
                mma_fp(sacc[mf][3], af[mf], bf1 + 2);
            }
        }

        // ---- epilogue: s = clip(d + w') -> exp -> P (fp16 smem), rsum ----
#pragma unroll
        for (int mf = 0; mf < 4; mf++)
#pragma unroll
            for (int hf = 0; hf < 2; hf++) {
                int row = swm + mf * 16 + hf * 8 + gr;
                float rs = 0.0f;
#pragma unroll
                for (int nf = 0; nf < 4; nf++) {
                    int col = swn + nf * 8 + tg2;
                    uint32_t wp = *(uint32_t*)(sm + STG + st * STG_SZ + SOW + (row * VST + col) * 2);
                    short2 ws = *(short2*)&wp;
                    float s0 = sacc[mf][nf][hf * 2]     + (float)ws.x * (1.0f / 2048.0f);
                    float s1 = sacc[mf][nf][hf * 2 + 1] + (float)ws.y * (1.0f / 2048.0f);
                    s0 = fminf(fmaxf(s0, -10.0f), 10.0f);
                    s1 = fminf(fmaxf(s1, -10.0f), 10.0f);
                    float e0 = __expf(s0), e1 = __expf(s1);
                    rs += e0 + e1;
                    *(__half2*)(sm + OP + (row * VST + col) * 2) = __floats2half2_rn(e0, e1);
                }
                rsum[mf * 2 + hf] += rs;
            }
        __syncthreads();   // P visible to all warps

        // ---- PV phase: ctx += P * Vt (1-pass fp16) ----
#pragma unroll
        for (int ks = 0; ks < 8; ks++) {
            uint32_t af[2][4], bf0[4], bf1[4];
#pragma unroll
            for (int mf = 0; mf < 2; mf++)
                ldmx4(af[mf], sb + OP + ((pwm + mf * 16 + arow) * VST + ks * 16 + ahalf * 8) * 2);
            ldmxB4(bf0, base + SOV, VST, pwn, 0, ks * 16, lane);
            ldmxB4(bf1, base + SOV, VST, pwn, 1, ks * 16, lane);
#pragma unroll
            for (int mf = 0; mf < 2; mf++) {
                mma_fp(ctx[mf][0], af[mf], bf0);
                mma_fp(ctx[mf][1], af[mf], bf0 + 2);
                mma_fp(ctx[mf][2], af[mf], bf1);
                mma_fp(ctx[mf][3], af[mf], bf1 + 2);
            }
        }
        // next iteration's top CP_WAIT0 + __syncthreads protects P/stage reuse
    }

    // ---- row sums: quad reduce + cross-warp via smem ----
#pragma unroll
    for (int r = 0; r < 8; r++) {
        rsum[r] += __shfl_xor_sync(0xffffffffu, rsum[r], 1);
        rsum[r] += __shfl_xor_sync(0xffffffffu, rsum[r], 2);
    }
    float* Sred = (float*)(sm + OSRED);
    if ((lane & 3) == 0) {
#pragma unroll
        for (int mf = 0; mf < 4; mf++)
#pragma unroll
            for (int hf = 0; hf < 2; hf++)
                Sred[(wid & 3) * 128 + swm + mf * 16 + hf * 8 + gr] = rsum[mf * 2 + hf];
    }
    __syncthreads();
    if (tid < 128) {
        float t = Sred[tid] + Sred[128 + tid] + Sred[256 + tid] + Sred[384 + tid];
        Sred[tid] = 0.25f / t;   // includes head-mean
    }
    __syncthreads();

    // ---- writeout ----
#pragma unroll
    for (int mf = 0; mf < 2; mf++)
#pragma unroll
        for (int hf = 0; hf < 2; hf++) {
            int row = pwm + mf * 16 + hf * 8 + gr;
            float sc = Sred[row];
#pragma unroll
            for (int nf = 0; nf < 4; nf++) {
                float2 v;
                v.x = ctx[mf][nf][hf * 2] * sc;
                v.y = ctx[mf][nf][hf * 2 + 1] * sc;
                *(float2*)(&CtxHd[h][(size_t)(a0 + row) * 64 + pwn + nf * 8 + tg2]) = v;
            }
        }
}

// ---------------- combine ----------------
__global__ void combine_kernel(float* __restrict__ out) {
    int idx = blockIdx.x * 256 + threadIdx.x;
    int a = idx >> 6, j = idx & 63;
    out[idx] = CtxHd[0][idx] + CtxHd[1][idx] + CtxHd[2][idx] + CtxHd[3][idx];
    if (j == 0) out[NA * DK + a] = 1.0f;   // influence == 1 exactly
}

extern "C" void kernel_launch(void* const* d_in, const int* in_sizes, int n_in,
                              void* d_out, int out_size) {
    const float* a_z    = (const float*)d_in[0];
    const float* bv_z   = (const float*)d_in[1];
    const int*   mask   = (const int*)d_in[2];
    const float* weight = (const float*)d_in[3];
    const float* Wq     = (const float*)d_in[4];
    const float* Wk     = (const float*)d_in[5];
    const float* Wv     = (const float*)d_in[6];
    float* out = (float*)d_out;

    __nv_bfloat16 *ah, *al, *bh, *bl, *wh, *wl;
    __half *qh, *kh, *vth;
    cudaGetSymbolAddress((void**)&ah, AhB);  cudaGetSymbolAddress((void**)&al, AlB);
    cudaGetSymbolAddress((void**)&bh, BhB);  cudaGetSymbolAddress((void**)&bl, BlB);
    cudaGetSymbolAddress((void**)&wh, WHb);  cudaGetSymbolAddress((void**)&wl, WLb);
    cudaGetSymbolAddress((void**)&qh, QhB);
    cudaGetSymbolAddress((void**)&kh, KhB);
    cudaGetSymbolAddress((void**)&vth, VtH);

    split_kernel<<<NA * D / 256, 256>>>(a_z, ah, al, NA * D, 1, 1.0f);
    split_kernel<<<NB * D / 256, 256>>>(bv_z, bh, bl, NB * D, 1, 1.0f);
    split_kernel<<<D * D / 256, 256>>>(Wq, wh + 0 * D * D, wl + 0 * D * D, D * D, 0, 0.125f);
    split_kernel<<<D * D / 256, 256>>>(Wk, wh + 1 * D * D, wl + 1 * D * D, D * D, 0, 1.0f);
    split_kernel<<<D * D / 256, 256>>>(Wv, wh + 2 * D * D, wl + 2 * D * D, D * D, 0, 1.0f);

    prep_w<<<NA * NB / (256 * 8), 256>>>(mask, weight);

    int proj_smem = (2 * 128 * QST + 2 * 64 * QST) * 2;   // 55296
    cudaFuncSetAttribute(proj_mma<0>, cudaFuncAttributeMaxDynamicSharedMemorySize, proj_smem);
    cudaFuncSetAttribute(proj_mma<1>, cudaFuncAttributeMaxDynamicSharedMemorySize, proj_smem);
    dim3 pg(32, 4);
    proj_mma<0><<<pg, 256, proj_smem>>>(ah, al, wh + 0 * D * D, wl + 0 * D * D, qh);
    proj_mma<0><<<pg, 256, proj_smem>>>(bh, bl, wh + 1 * D * D, wl + 1 * D * D, kh);
    proj_mma<1><<<pg, 256, proj_smem>>>(bh, bl, wh + 2 * D * D, wl + 2 * D * D, vth);

    cudaFuncSetAttribute(attn_fused, cudaFuncAttributeMaxDynamicSharedMemorySize, FUSED_SMEM);
    attn_fused<<<dim3(32, 4), 256, FUSED_SMEM>>>();

    combine_kernel<<<NA * DK / 256, 256>>>(out);
}